// round 11
// baseline (speedup 1.0000x reference)
#include <cuda_runtime.h>
#include <cuda_fp16.h>
#include <cstdint>
#include <math_constants.h>

// Problem constants
#define CDIM 512
#define NHEAD 16
#define HD 32
#define LTOK 49
#define BNW 4096
#define MROWS (BNW * LTOK)            // 200704
#define NQKV (3 * CDIM)               // 1536
#define SLAB (LTOK * HD)              // 1568
#define WINSTRIDE (NHEAD * SLAB)      // 25088
#define PARTSTRIDE ((size_t)CDIM * MROWS)
#define KDIM 512
#define KITER (KDIM / 16)             // 32 iters of K=16
#define LP 52                          // padded token dim
#define LL (LTOK * LTOK)               // 2401

// Scratch (device globals — no allocation)
__device__ __half g_qkh[(size_t)1024 * MROWS];      // Q,K hi plane (flat slabs)
__device__ __half g_qkl[(size_t)1024 * MROWS];      // Q,K lo plane
__device__ __half g_vh[(size_t)CDIM * MROWS];       // V channel-major fp16
__device__ __half g_xhi[(size_t)MROWS * CDIM];      // x split hi/lo
__device__ __half g_xlo[(size_t)MROWS * CDIM];
__device__ __half g_ohi[(size_t)MROWS * CDIM];      // attn out, fp16 (hi only)
__device__ __half g_whi1[(size_t)NQKV * KDIM];      // w_qkv^T hi/lo [N][K]
__device__ __half g_wlo1[(size_t)NQKV * KDIM];
__device__ __half g_whi2[(size_t)CDIM * KDIM];      // w_proj^T hi (1-term)
__device__ __half g_wlo2[(size_t)CDIM * KDIM];
__device__ __half g_bmh[64 * NHEAD * LL];           // fused bias+mask, fp16

// ---------------------------------------------------------------------------
// PTX helpers (sm_80-era ISA — tcgen05 unavailable at compute_103)
// ---------------------------------------------------------------------------
__device__ __forceinline__ uint32_t smem_u32(const void* p) {
    uint32_t a;
    asm("{ .reg .u64 t; cvta.to.shared.u64 t, %1; cvt.u32.u64 %0, t; }"
        : "=r"(a) : "l"(p));
    return a;
}
__device__ __forceinline__ void cp_async16(uint32_t smem, const void* g) {
    asm volatile("cp.async.cg.shared.global [%0], [%1], 16;"
                 :: "r"(smem), "l"(g) : "memory");
}
__device__ __forceinline__ void cp_commit() {
    asm volatile("cp.async.commit_group;" ::: "memory");
}
template <int N>
__device__ __forceinline__ void cp_wait() {
    asm volatile("cp.async.wait_group %0;" :: "n"(N) : "memory");
}
__device__ __forceinline__ void ldsm_x4(uint32_t& r0, uint32_t& r1,
                                        uint32_t& r2, uint32_t& r3,
                                        uint32_t addr) {
    asm volatile("ldmatrix.sync.aligned.m8n8.x4.shared.b16 {%0,%1,%2,%3}, [%4];"
                 : "=r"(r0), "=r"(r1), "=r"(r2), "=r"(r3) : "r"(addr));
}
__device__ __forceinline__ void mma_f16(float* d, const uint32_t* a,
                                        const uint32_t* b) {
    asm volatile(
        "mma.sync.aligned.m16n8k16.row.col.f32.f16.f16.f32 "
        "{%0,%1,%2,%3}, {%4,%5,%6,%7}, {%8,%9}, {%0,%1,%2,%3};"
        : "+f"(d[0]), "+f"(d[1]), "+f"(d[2]), "+f"(d[3])
        : "r"(a[0]), "r"(a[1]), "r"(a[2]), "r"(a[3]), "r"(b[0]), "r"(b[1]));
}

#define STAGE_BYTES 16384
#define NSTAGE 4
#define DYN_SMEM 66560   // max(4*16384, 8 warps * 32*65*4 bounce)

__device__ __forceinline__ uint32_t sw16(int row, int c) {
    return (uint32_t)row * 32u + (uint32_t)((c ^ ((row >> 2) & 1)) << 4);
}

// ---------------------------------------------------------------------------
// x -> hi/lo fp16 split (elementwise)
// ---------------------------------------------------------------------------
__global__ __launch_bounds__(256) void split_x_kernel(const float* __restrict__ src) {
    size_t i = ((size_t)blockIdx.x * 256 + threadIdx.x) * 4;
    float4 v = *(const float4*)(src + i);
    __half h0 = __float2half_rn(v.x), h1 = __float2half_rn(v.y);
    __half h2 = __float2half_rn(v.z), h3 = __float2half_rn(v.w);
    __half l0 = __float2half_rn(v.x - __half2float(h0));
    __half l1 = __float2half_rn(v.y - __half2float(h1));
    __half l2 = __float2half_rn(v.z - __half2float(h2));
    __half l3 = __float2half_rn(v.w - __half2float(h3));
    __half2 hh[2] = {__halves2half2(h0, h1), __halves2half2(h2, h3)};
    __half2 ll[2] = {__halves2half2(l0, l1), __halves2half2(l2, l3)};
    *(uint2*)(g_xhi + i) = *(uint2*)hh;
    *(uint2*)(g_xlo + i) = *(uint2*)ll;
}

// ---------------------------------------------------------------------------
// Weight transpose + split: src[k*N + n] -> dst_{hi,lo}[n*K + k]
// ---------------------------------------------------------------------------
template <int SEL>
__global__ void wtrans_kernel(const float* __restrict__ src, int K, int N) {
    __half* dhi = (SEL == 1) ? g_whi1 : g_whi2;
    __half* dlo = (SEL == 1) ? g_wlo1 : g_wlo2;
    __shared__ float t[32][33];
    int n0 = blockIdx.x * 32, k0 = blockIdx.y * 32;
    int x = threadIdx.x, y = threadIdx.y;
    #pragma unroll
    for (int i = y; i < 32; i += 8)
        t[i][x] = src[(size_t)(k0 + i) * N + n0 + x];
    __syncthreads();
    #pragma unroll
    for (int i = y; i < 32; i += 8) {
        float v = t[x][i];
        __half h = __float2half_rn(v);
        __half l = __float2half_rn(v - __half2float(h));
        dhi[(size_t)(n0 + i) * K + k0 + x] = h;
        dlo[(size_t)(n0 + i) * K + k0 + x] = l;
    }
}

// ---------------------------------------------------------------------------
// Fused bias+mask precompute (fp16 output)
// ---------------------------------------------------------------------------
__global__ __launch_bounds__(256) void biasmask_kernel(
    const float* __restrict__ mask,
    const float* __restrict__ bias_table,
    const int*   __restrict__ index_table)
{
    int wh = blockIdx.x;
    int w = wh >> 4, h = wh & 15;
    const float* mrow = mask + (size_t)w * LL;
    __half* dst = g_bmh + (size_t)wh * LL;
    for (int o = threadIdx.x; o < LL; o += 256)
        dst[o] = __float2half_rn(bias_table[index_table[o] * NHEAD + h] + mrow[o]);
}

// ---------------------------------------------------------------------------
// fp16 split GEMM, variable term count (256 thr, 2x4 warps, 64x32 warp tile).
// TERMS=3 MODE=1: QK columns -> hi/lo fp16 scatter to g_qkh/g_qkl
// TERMS=1 MODE=1: V columns  -> fp16 scatter to g_vh
// TERMS=1 MODE=2: proj       -> row-major fp32 to C
// ---------------------------------------------------------------------------
template <int MODE, int TERMS>
__global__ __launch_bounds__(256) void gemm_f16x3(
    const float* __restrict__ bias, float* __restrict__ C, int N, int bnOff)
{
    extern __shared__ char smem[];
    const __half* Ahi = (MODE == 1) ? g_xhi : g_ohi;
    const __half* Alo = (MODE == 1) ? g_xlo : g_ohi;   // dummy when TERMS<3
    const __half* Bhi = (MODE == 1) ? g_whi1 : g_whi2;
    const __half* Blo = (MODE == 1) ? g_wlo1 : g_wlo2;

    const int tid = threadIdx.x;
    const int lane = tid & 31, wid = tid >> 5;
    const int warpM = wid & 1, warpN = wid >> 1;   // 2 x 4 warps, 64x32 tiles
    const int bm = blockIdx.y, bn = blockIdx.x + bnOff;
    const uint32_t sbase = smem_u32(smem);

    const int grow = tid >> 1, gch = tid & 1;
    const uint32_t soff = sw16(grow, gch);
    const __half* gAhi = Ahi + (size_t)(bm * 128 + grow) * KDIM + gch * 8;
    const __half* gAlo = Alo + (size_t)(bm * 128 + grow) * KDIM + gch * 8;
    const __half* gBhi = Bhi + (size_t)(bn * 128 + grow) * KDIM + gch * 8;
    const __half* gBlo = Blo + (size_t)(bn * 128 + grow) * KDIM + gch * 8;

    float acc[4][4][4];
    #pragma unroll
    for (int i = 0; i < 4; i++)
        #pragma unroll
        for (int j = 0; j < 4; j++)
            #pragma unroll
            for (int q = 0; q < 4; q++) acc[i][j][q] = 0.f;

    #pragma unroll
    for (int s = 0; s < NSTAGE - 1; s++) {
        uint32_t st = sbase + s * STAGE_BYTES;
        int k0 = s * 16;
        cp_async16(st + soff, gAhi + k0);
        if (TERMS >= 3) cp_async16(st + 4096 + soff, gAlo + k0);
        cp_async16(st + 8192 + soff, gBhi + k0);
        if (TERMS >= 2) cp_async16(st + 12288 + soff, gBlo + k0);
        cp_commit();
    }

    const int lrow = lane & 15, lhalf = lane >> 4;
    uint32_t offA[4], offB[2];
    #pragma unroll
    for (int mt = 0; mt < 4; mt++)
        offA[mt] = sw16(warpM * 64 + mt * 16 + lrow, lhalf);
    #pragma unroll
    for (int nt2 = 0; nt2 < 2; nt2++)
        offB[nt2] = sw16(warpN * 32 + nt2 * 16 + lrow, lhalf);

    for (int it = 0; it < KITER; it++) {
        cp_wait<NSTAGE - 2>();
        __syncthreads();

        if (it + NSTAGE - 1 < KITER) {
            int s = (it + NSTAGE - 1) % NSTAGE;
            uint32_t st = sbase + s * STAGE_BYTES;
            int k0 = (it + NSTAGE - 1) * 16;
            cp_async16(st + soff, gAhi + k0);
            if (TERMS >= 3) cp_async16(st + 4096 + soff, gAlo + k0);
            cp_async16(st + 8192 + soff, gBhi + k0);
            if (TERMS >= 2) cp_async16(st + 12288 + soff, gBlo + k0);
        }
        cp_commit();

        const uint32_t st = sbase + (it % NSTAGE) * STAGE_BYTES;

        uint32_t ah[4][4], al[4][4], bh[4][2], bl[4][2];
        #pragma unroll
        for (int mt = 0; mt < 4; mt++) {
            ldsm_x4(ah[mt][0], ah[mt][1], ah[mt][2], ah[mt][3], st + offA[mt]);
            if (TERMS >= 3)
                ldsm_x4(al[mt][0], al[mt][1], al[mt][2], al[mt][3],
                        st + 4096 + offA[mt]);
        }
        #pragma unroll
        for (int nt2 = 0; nt2 < 2; nt2++) {
            uint32_t r0, r1, r2, r3;
            ldsm_x4(r0, r1, r2, r3, st + 8192 + offB[nt2]);
            bh[nt2 * 2 + 0][0] = r0; bh[nt2 * 2 + 0][1] = r2;
            bh[nt2 * 2 + 1][0] = r1; bh[nt2 * 2 + 1][1] = r3;
            if (TERMS >= 2) {
                ldsm_x4(r0, r1, r2, r3, st + 12288 + offB[nt2]);
                bl[nt2 * 2 + 0][0] = r0; bl[nt2 * 2 + 0][1] = r2;
                bl[nt2 * 2 + 1][0] = r1; bl[nt2 * 2 + 1][1] = r3;
            }
        }
        #pragma unroll
        for (int mt = 0; mt < 4; mt++)
            #pragma unroll
            for (int nt = 0; nt < 4; nt++) {
                mma_f16(acc[mt][nt], ah[mt], bh[nt]);
                if (TERMS >= 2) mma_f16(acc[mt][nt], ah[mt], bl[nt]);
                if (TERMS >= 3) mma_f16(acc[mt][nt], al[mt], bh[nt]);
            }
    }

    cp_wait<0>();
    __syncthreads();   // before smem reuse as bounce

    if (MODE == 2) {
        #pragma unroll
        for (int mt = 0; mt < 4; mt++) {
            #pragma unroll
            for (int nt = 0; nt < 4; nt++) {
                int m0 = bm * 128 + warpM * 64 + mt * 16 + (lane >> 2);
                int n0 = bn * 128 + warpN * 32 + nt * 8 + (lane & 3) * 2;
                float2 bv = *(const float2*)(bias + n0);
                float2 v0 = make_float2(acc[mt][nt][0] + bv.x, acc[mt][nt][1] + bv.y);
                float2 v1 = make_float2(acc[mt][nt][2] + bv.x, acc[mt][nt][3] + bv.y);
                *(float2*)(C + (size_t)m0 * N + n0) = v0;
                *(float2*)(C + (size_t)(m0 + 8) * N + n0) = v1;
            }
        }
    } else {
        float* bounce = (float*)smem + wid * (32 * 65);
        #pragma unroll
        for (int mt = 0; mt < 4; mt++) {
            #pragma unroll
            for (int nt = 0; nt < 4; nt++) {
                int nl = nt * 8 + (lane & 3) * 2;
                int ml = mt * 16 + (lane >> 2);
                bounce[nl * 65 + ml]            = acc[mt][nt][0];
                bounce[(nl + 1) * 65 + ml]      = acc[mt][nt][1];
                bounce[nl * 65 + ml + 8]        = acc[mt][nt][2];
                bounce[(nl + 1) * 65 + ml + 8]  = acc[mt][nt][3];
            }
        }
        __syncwarp();
        int col = bn * 128 + warpN * 32 + lane;
        float bv = bias[col];
        const float* src = bounce + lane * 65;
        if (TERMS == 1) {
            // V columns: fp16 scatter to g_vh
            __half* dst = g_vh + (size_t)(col - 1024) * MROWS
                        + bm * 128 + warpM * 64;
            #pragma unroll
            for (int q = 0; q < 16; q++) {
                __half h[4];
                h[0] = __float2half_rn(src[q * 4 + 0] + bv);
                h[1] = __float2half_rn(src[q * 4 + 1] + bv);
                h[2] = __float2half_rn(src[q * 4 + 2] + bv);
                h[3] = __float2half_rn(src[q * 4 + 3] + bv);
                *(uint2*)(dst + q * 4) = *(uint2*)h;
            }
        } else {
            // Q,K columns: hi/lo fp16 planes
            size_t off = (size_t)col * MROWS + bm * 128 + warpM * 64;
            __half* dh = g_qkh + off;
            __half* dl = g_qkl + off;
            #pragma unroll
            for (int q = 0; q < 16; q++) {
                __half hv[4], lv[4];
                #pragma unroll
                for (int j = 0; j < 4; j++) {
                    float v = src[q * 4 + j] + bv;
                    hv[j] = __float2half_rn(v);
                    lv[j] = __float2half_rn(v - __half2float(hv[j]));
                }
                *(uint2*)(dh + q * 4) = *(uint2*)hv;
                *(uint2*)(dl + q * 4) = *(uint2*)lv;
            }
        }
    }
}

// ---------------------------------------------------------------------------
// Attention: HMMA 3-term score phase (Qh/Ql x Kh/Kl), smem softmax, FMA PV.
// Operand tiles use 80B row stride -> conflict-free ldmatrix, no swizzle.
// ---------------------------------------------------------------------------
__global__ __launch_bounds__(256) void attn_kernel()
{
    __shared__ __align__(16) __half sQh[64 * 40];
    __shared__ __align__(16) __half sQl[64 * 40];
    __shared__ __align__(16) __half sKh[64 * 40];
    __shared__ __align__(16) __half sKl[64 * 40];
    __shared__ __align__(16) __half sVh[SLAB];
    __shared__ float sS[LP * LP];

    int tid = threadIdx.x;
    int b2 = blockIdx.x >> 4;
    int h  = blockIdx.x & 15;

    size_t base = (size_t)b2 * WINSTRIDE + (size_t)h * SLAB;
    const __half* Qh = g_qkh + base;
    const __half* Ql = g_qkl + base;
    const __half* Kh = g_qkh + PARTSTRIDE + base;
    const __half* Kl = g_qkl + PARTSTRIDE + base;
    const __half* Vg = g_vh + base;
    const __half* bm = g_bmh + ((size_t)(b2 & 63) * NHEAD + h) * LL;

    // Load slabs: 196 uint4 per plane; dst row stride 80B
    if (tid < 196) {
        int row = tid >> 2, ch = tid & 3;
        uint32_t d = (uint32_t)row * 80u + (uint32_t)ch * 16u;
        *(uint4*)((char*)sQh + d) = ((const uint4*)Qh)[tid];
        *(uint4*)((char*)sQl + d) = ((const uint4*)Ql)[tid];
        *(uint4*)((char*)sKh + d) = ((const uint4*)Kh)[tid];
        *(uint4*)((char*)sKl + d) = ((const uint4*)Kl)[tid];
        ((uint4*)sVh)[tid] = ((const uint4*)Vg)[tid];
    }
    __syncthreads();

    // Scores: 8 warps, warp w -> m-tile (w>>1), n-half (w&1)
    {
        int w = tid >> 5, lane = tid & 31;
        int mt = w >> 1, nh = w & 1;
        int lrow = lane & 15, lhalf = lane >> 4;
        uint32_t uQh = smem_u32(sQh), uQl = smem_u32(sQl);
        uint32_t uKh = smem_u32(sKh), uKl = smem_u32(sKl);
        uint32_t aoff  = (uint32_t)(mt * 16 + lrow) * 80u + lhalf * 16u;
        uint32_t boff0 = (uint32_t)(nh * 32 + lrow) * 80u + lhalf * 16u;
        uint32_t boff1 = boff0 + 16u * 80u;

        float acc[4][4];
        #pragma unroll
        for (int i = 0; i < 4; i++)
            #pragma unroll
            for (int j = 0; j < 4; j++) acc[i][j] = 0.f;

        #pragma unroll
        for (int ks = 0; ks < 2; ks++) {
            uint32_t kb = ks * 32u;
            uint32_t qh[4], ql[4], kh[4][2], kl[4][2];
            ldsm_x4(qh[0], qh[1], qh[2], qh[3], uQh + aoff + kb);
            ldsm_x4(ql[0], ql[1], ql[2], ql[3], uQl + aoff + kb);
            uint32_t r0, r1, r2, r3;
            ldsm_x4(r0, r1, r2, r3, uKh + boff0 + kb);
            kh[0][0] = r0; kh[0][1] = r2; kh[1][0] = r1; kh[1][1] = r3;
            ldsm_x4(r0, r1, r2, r3, uKh + boff1 + kb);
            kh[2][0] = r0; kh[2][1] = r2; kh[3][0] = r1; kh[3][1] = r3;
            ldsm_x4(r0, r1, r2, r3, uKl + boff0 + kb);
            kl[0][0] = r0; kl[0][1] = r2; kl[1][0] = r1; kl[1][1] = r3;
            ldsm_x4(r0, r1, r2, r3, uKl + boff1 + kb);
            kl[2][0] = r0; kl[2][1] = r2; kl[3][0] = r1; kl[3][1] = r3;
            #pragma unroll
            for (int nt = 0; nt < 4; nt++) {
                mma_f16(acc[nt], qh, kh[nt]);
                mma_f16(acc[nt], qh, kl[nt]);
                mma_f16(acc[nt], ql, kh[nt]);
            }
        }

        // store S + bias+mask (discard padded rows/cols)
        int rbase = mt * 16 + (lane >> 2);
        #pragma unroll
        for (int nt = 0; nt < 4; nt++) {
            int c = nh * 32 + nt * 8 + (lane & 3) * 2;
            #pragma unroll
            for (int hf = 0; hf < 2; hf++) {
                int r = rbase + hf * 8;
                if (r < LTOK) {
                    if (c < LTOK)
                        sS[r * LP + c] = acc[nt][hf * 2 + 0]
                            + __half2float(bm[r * LTOK + c]);
                    if (c + 1 < LTOK)
                        sS[r * LP + c + 1] = acc[nt][hf * 2 + 1]
                            + __half2float(bm[r * LTOK + c + 1]);
                }
            }
        }
    }
    __syncthreads();

    // Softmax per row (warp per row)
    int warp = tid >> 5, lane = tid & 31;
    for (int row = warp; row < LTOK; row += 8) {
        float* s = sS + row * LP;
        float e0 = s[lane];
        float e1 = (lane + 32 < LTOK) ? s[lane + 32] : -CUDART_INF_F;
        float mx = fmaxf(e0, e1);
        #pragma unroll
        for (int off = 16; off; off >>= 1)
            mx = fmaxf(mx, __shfl_xor_sync(0xffffffffu, mx, off));
        float p0 = __expf(e0 - mx);
        float p1 = (lane + 32 < LTOK) ? __expf(e1 - mx) : 0.f;
        float sum = p0 + p1;
        #pragma unroll
        for (int off = 16; off; off >>= 1)
            sum += __shfl_xor_sync(0xffffffffu, sum, off);
        float inv = 1.f / sum;
        s[lane] = p0 * inv;
        if (lane + 32 < LTOK) s[lane + 32] = p1 * inv;
    }
    __syncthreads();

    // PV: 13(l) x 16(d) grid of 4x2 tiles (208 units)
    if (tid < 208) {
        int dt = tid & 15, lt = tid >> 4;
        int l0 = lt * 4, d0 = dt * 2;
        const __half2* v2 = (const __half2*)sVh;
        float acc[4][2];
        #pragma unroll
        for (int i = 0; i < 4; i++) { acc[i][0] = 0.f; acc[i][1] = 0.f; }
        for (int m = 0; m < LTOK; m++) {
            float2 vf = __half22float2(v2[m * 16 + dt]);
            float p0 = sS[(l0 + 0) * LP + m];
            float p1 = sS[(l0 + 1) * LP + m];
            float p2 = sS[(l0 + 2) * LP + m];
            float p3 = sS[(l0 + 3) * LP + m];
            acc[0][0] = fmaf(p0, vf.x, acc[0][0]);
            acc[0][1] = fmaf(p0, vf.y, acc[0][1]);
            acc[1][0] = fmaf(p1, vf.x, acc[1][0]);
            acc[1][1] = fmaf(p1, vf.y, acc[1][1]);
            acc[2][0] = fmaf(p2, vf.x, acc[2][0]);
            acc[2][1] = fmaf(p2, vf.y, acc[2][1]);
            acc[3][0] = fmaf(p3, vf.x, acc[3][0]);
            acc[3][1] = fmaf(p3, vf.y, acc[3][1]);
        }
        #pragma unroll
        for (int i = 0; i < 4; i++) {
            int l = l0 + i;
            if (l < LTOK) {
                size_t oidx = ((size_t)b2 * LTOK + l) * CDIM + h * HD + d0;
                *(__half2*)(g_ohi + oidx) = __floats2half2_rn(acc[i][0], acc[i][1]);
            }
        }
    }
}

// ---------------------------------------------------------------------------
extern "C" void kernel_launch(void* const* d_in, const int* in_sizes, int n_in,
                              void* d_out, int out_size)
{
    const float* x           = (const float*)d_in[0];
    const float* mask        = (const float*)d_in[1];
    const float* w_qkv       = (const float*)d_in[2];
    const float* b_qkv       = (const float*)d_in[3];
    const float* w_proj      = (const float*)d_in[4];
    const float* b_proj      = (const float*)d_in[5];
    const float* bias_table  = (const float*)d_in[6];
    const int*   index_table = (const int*)d_in[7];
    float* out = (float*)d_out;

    cudaFuncSetAttribute(gemm_f16x3<1, 3>, cudaFuncAttributeMaxDynamicSharedMemorySize, DYN_SMEM);
    cudaFuncSetAttribute(gemm_f16x3<1, 1>, cudaFuncAttributeMaxDynamicSharedMemorySize, DYN_SMEM);
    cudaFuncSetAttribute(gemm_f16x3<2, 1>, cudaFuncAttributeMaxDynamicSharedMemorySize, DYN_SMEM);

    // 0) weight transpose+split, x split, fused bias+mask table (fp16)
    wtrans_kernel<1><<<dim3(NQKV / 32, KDIM / 32), dim3(32, 8)>>>(w_qkv, KDIM, NQKV);
    wtrans_kernel<2><<<dim3(CDIM / 32, KDIM / 32), dim3(32, 8)>>>(w_proj, KDIM, CDIM);
    split_x_kernel<<<((size_t)MROWS * CDIM) / 4 / 256, 256>>>(x);
    biasmask_kernel<<<64 * NHEAD, 256>>>(mask, bias_table, index_table);

    // 1a) QK columns (0..1023): 3-term, hi/lo fp16 scatter
    gemm_f16x3<1, 3><<<dim3(8, MROWS / 128), 256, DYN_SMEM>>>(b_qkv, nullptr, NQKV, 0);
    // 1b) V columns (1024..1535): 1-term fp16 scatter
    gemm_f16x3<1, 1><<<dim3(4, MROWS / 128), 256, DYN_SMEM>>>(b_qkv, nullptr, NQKV, 8);

    // 2) fused window attention (HMMA scores)
    attn_kernel<<<BNW * NHEAD, 256>>>();

    // 3) projection GEMM: 1-term
    gemm_f16x3<2, 1><<<dim3(4, MROWS / 128), 256, DYN_SMEM>>>(b_proj, out, CDIM, 0);
}

// round 12
// speedup vs baseline: 1.0488x; 1.0488x over previous
#include <cuda_runtime.h>
#include <cuda_fp16.h>
#include <cstdint>
#include <math_constants.h>

// Problem constants
#define CDIM 512
#define NHEAD 16
#define HD 32
#define LTOK 49
#define BNW 4096
#define MROWS (BNW * LTOK)            // 200704
#define NQKV (3 * CDIM)               // 1536
#define SLAB (LTOK * HD)              // 1568
#define WINSTRIDE (NHEAD * SLAB)      // 25088
#define PARTSTRIDE ((size_t)CDIM * MROWS)
#define KDIM 512
#define KITER (KDIM / 16)             // 32 iters of K=16
#define LP 52                          // padded token dim
#define LL (LTOK * LTOK)               // 2401

// Scratch (device globals — no allocation)
__device__ float  g_qkvT[(size_t)1024 * MROWS];     // Q,K channel-major fp32
__device__ __half g_vh[(size_t)CDIM * MROWS];       // V channel-major fp16
__device__ __half g_xhi[(size_t)MROWS * CDIM];      // x split hi/lo
__device__ __half g_xlo[(size_t)MROWS * CDIM];
__device__ __half g_ohi[(size_t)MROWS * CDIM];      // attn out, fp16 (hi only)
__device__ __half g_whi1[(size_t)NQKV * KDIM];      // w_qkv^T hi/lo [N][K]
__device__ __half g_wlo1[(size_t)NQKV * KDIM];
__device__ __half g_whi2[(size_t)CDIM * KDIM];      // w_proj^T hi (1-term)
__device__ __half g_wlo2[(size_t)CDIM * KDIM];
__device__ __half g_bmh[64 * NHEAD * LL];           // fused bias+mask, fp16

// ---------------------------------------------------------------------------
// PTX helpers (sm_80-era ISA — tcgen05 unavailable at compute_103)
// ---------------------------------------------------------------------------
__device__ __forceinline__ uint32_t smem_u32(const void* p) {
    uint32_t a;
    asm("{ .reg .u64 t; cvta.to.shared.u64 t, %1; cvt.u32.u64 %0, t; }"
        : "=r"(a) : "l"(p));
    return a;
}
__device__ __forceinline__ void cp_async16(uint32_t smem, const void* g) {
    asm volatile("cp.async.cg.shared.global [%0], [%1], 16;"
                 :: "r"(smem), "l"(g) : "memory");
}
__device__ __forceinline__ void cp_commit() {
    asm volatile("cp.async.commit_group;" ::: "memory");
}
template <int N>
__device__ __forceinline__ void cp_wait() {
    asm volatile("cp.async.wait_group %0;" :: "n"(N) : "memory");
}
__device__ __forceinline__ void ldsm_x4(uint32_t& r0, uint32_t& r1,
                                        uint32_t& r2, uint32_t& r3,
                                        uint32_t addr) {
    asm volatile("ldmatrix.sync.aligned.m8n8.x4.shared.b16 {%0,%1,%2,%3}, [%4];"
                 : "=r"(r0), "=r"(r1), "=r"(r2), "=r"(r3) : "r"(addr));
}
__device__ __forceinline__ void ldsm_x4_trans(uint32_t& r0, uint32_t& r1,
                                              uint32_t& r2, uint32_t& r3,
                                              uint32_t addr) {
    asm volatile("ldmatrix.sync.aligned.m8n8.x4.trans.shared.b16 {%0,%1,%2,%3}, [%4];"
                 : "=r"(r0), "=r"(r1), "=r"(r2), "=r"(r3) : "r"(addr));
}
__device__ __forceinline__ void mma_f16(float* d, const uint32_t* a,
                                        const uint32_t* b) {
    asm volatile(
        "mma.sync.aligned.m16n8k16.row.col.f32.f16.f16.f32 "
        "{%0,%1,%2,%3}, {%4,%5,%6,%7}, {%8,%9}, {%0,%1,%2,%3};"
        : "+f"(d[0]), "+f"(d[1]), "+f"(d[2]), "+f"(d[3])
        : "r"(a[0]), "r"(a[1]), "r"(a[2]), "r"(a[3]), "r"(b[0]), "r"(b[1]));
}

#define STAGE_BYTES 16384
#define NSTAGE 4
#define DYN_SMEM 66560   // max(4*16384, 8 warps * 32*65*4 bounce)

__device__ __forceinline__ uint32_t sw16(int row, int c) {
    return (uint32_t)row * 32u + (uint32_t)((c ^ ((row >> 2) & 1)) << 4);
}

// ---------------------------------------------------------------------------
// x -> hi/lo fp16 split (elementwise)
// ---------------------------------------------------------------------------
__global__ __launch_bounds__(256) void split_x_kernel(const float* __restrict__ src) {
    size_t i = ((size_t)blockIdx.x * 256 + threadIdx.x) * 4;
    float4 v = *(const float4*)(src + i);
    __half h0 = __float2half_rn(v.x), h1 = __float2half_rn(v.y);
    __half h2 = __float2half_rn(v.z), h3 = __float2half_rn(v.w);
    __half l0 = __float2half_rn(v.x - __half2float(h0));
    __half l1 = __float2half_rn(v.y - __half2float(h1));
    __half l2 = __float2half_rn(v.z - __half2float(h2));
    __half l3 = __float2half_rn(v.w - __half2float(h3));
    __half2 hh[2] = {__halves2half2(h0, h1), __halves2half2(h2, h3)};
    __half2 ll[2] = {__halves2half2(l0, l1), __halves2half2(l2, l3)};
    *(uint2*)(g_xhi + i) = *(uint2*)hh;
    *(uint2*)(g_xlo + i) = *(uint2*)ll;
}

// ---------------------------------------------------------------------------
// Weight transpose + split: src[k*N + n] -> dst_{hi,lo}[n*K + k]
// ---------------------------------------------------------------------------
template <int SEL>
__global__ void wtrans_kernel(const float* __restrict__ src, int K, int N) {
    __half* dhi = (SEL == 1) ? g_whi1 : g_whi2;
    __half* dlo = (SEL == 1) ? g_wlo1 : g_wlo2;
    __shared__ float t[32][33];
    int n0 = blockIdx.x * 32, k0 = blockIdx.y * 32;
    int x = threadIdx.x, y = threadIdx.y;
    #pragma unroll
    for (int i = y; i < 32; i += 8)
        t[i][x] = src[(size_t)(k0 + i) * N + n0 + x];
    __syncthreads();
    #pragma unroll
    for (int i = y; i < 32; i += 8) {
        float v = t[x][i];
        __half h = __float2half_rn(v);
        __half l = __float2half_rn(v - __half2float(h));
        dhi[(size_t)(n0 + i) * K + k0 + x] = h;
        dlo[(size_t)(n0 + i) * K + k0 + x] = l;
    }
}

// ---------------------------------------------------------------------------
// Fused bias+mask precompute (fp16 output)
// ---------------------------------------------------------------------------
__global__ __launch_bounds__(256) void biasmask_kernel(
    const float* __restrict__ mask,
    const float* __restrict__ bias_table,
    const int*   __restrict__ index_table)
{
    int wh = blockIdx.x;
    int w = wh >> 4, h = wh & 15;
    const float* mrow = mask + (size_t)w * LL;
    __half* dst = g_bmh + (size_t)wh * LL;
    for (int o = threadIdx.x; o < LL; o += 256)
        dst[o] = __float2half_rn(bias_table[index_table[o] * NHEAD + h] + mrow[o]);
}

// ---------------------------------------------------------------------------
// fp16 split GEMM, variable term count (256 thr, 2x4 warps, 64x32 warp tile).
// TERMS=3 MODE=1: QK columns -> fp32 scatter to g_qkvT
// TERMS=1 MODE=1: V columns  -> fp16 scatter to g_vh
// TERMS=1 MODE=2: proj       -> row-major fp32 to C
// ---------------------------------------------------------------------------
template <int MODE, int TERMS>
__global__ __launch_bounds__(256) void gemm_f16x3(
    const float* __restrict__ bias, float* __restrict__ C, int N, int bnOff)
{
    extern __shared__ char smem[];
    const __half* Ahi = (MODE == 1) ? g_xhi : g_ohi;
    const __half* Alo = (MODE == 1) ? g_xlo : g_ohi;   // dummy when TERMS<3
    const __half* Bhi = (MODE == 1) ? g_whi1 : g_whi2;
    const __half* Blo = (MODE == 1) ? g_wlo1 : g_wlo2;

    const int tid = threadIdx.x;
    const int lane = tid & 31, wid = tid >> 5;
    const int warpM = wid & 1, warpN = wid >> 1;   // 2 x 4 warps, 64x32 tiles
    const int bm = blockIdx.y, bn = blockIdx.x + bnOff;
    const uint32_t sbase = smem_u32(smem);

    const int grow = tid >> 1, gch = tid & 1;
    const uint32_t soff = sw16(grow, gch);
    const __half* gAhi = Ahi + (size_t)(bm * 128 + grow) * KDIM + gch * 8;
    const __half* gAlo = Alo + (size_t)(bm * 128 + grow) * KDIM + gch * 8;
    const __half* gBhi = Bhi + (size_t)(bn * 128 + grow) * KDIM + gch * 8;
    const __half* gBlo = Blo + (size_t)(bn * 128 + grow) * KDIM + gch * 8;

    float acc[4][4][4];
    #pragma unroll
    for (int i = 0; i < 4; i++)
        #pragma unroll
        for (int j = 0; j < 4; j++)
            #pragma unroll
            for (int q = 0; q < 4; q++) acc[i][j][q] = 0.f;

    #pragma unroll
    for (int s = 0; s < NSTAGE - 1; s++) {
        uint32_t st = sbase + s * STAGE_BYTES;
        int k0 = s * 16;
        cp_async16(st + soff, gAhi + k0);
        if (TERMS >= 3) cp_async16(st + 4096 + soff, gAlo + k0);
        cp_async16(st + 8192 + soff, gBhi + k0);
        if (TERMS >= 2) cp_async16(st + 12288 + soff, gBlo + k0);
        cp_commit();
    }

    const int lrow = lane & 15, lhalf = lane >> 4;
    uint32_t offA[4], offB[2];
    #pragma unroll
    for (int mt = 0; mt < 4; mt++)
        offA[mt] = sw16(warpM * 64 + mt * 16 + lrow, lhalf);
    #pragma unroll
    for (int nt2 = 0; nt2 < 2; nt2++)
        offB[nt2] = sw16(warpN * 32 + nt2 * 16 + lrow, lhalf);

    for (int it = 0; it < KITER; it++) {
        cp_wait<NSTAGE - 2>();
        __syncthreads();

        if (it + NSTAGE - 1 < KITER) {
            int s = (it + NSTAGE - 1) % NSTAGE;
            uint32_t st = sbase + s * STAGE_BYTES;
            int k0 = (it + NSTAGE - 1) * 16;
            cp_async16(st + soff, gAhi + k0);
            if (TERMS >= 3) cp_async16(st + 4096 + soff, gAlo + k0);
            cp_async16(st + 8192 + soff, gBhi + k0);
            if (TERMS >= 2) cp_async16(st + 12288 + soff, gBlo + k0);
        }
        cp_commit();

        const uint32_t st = sbase + (it % NSTAGE) * STAGE_BYTES;

        uint32_t ah[4][4], al[4][4], bh[4][2], bl[4][2];
        #pragma unroll
        for (int mt = 0; mt < 4; mt++) {
            ldsm_x4(ah[mt][0], ah[mt][1], ah[mt][2], ah[mt][3], st + offA[mt]);
            if (TERMS >= 3)
                ldsm_x4(al[mt][0], al[mt][1], al[mt][2], al[mt][3],
                        st + 4096 + offA[mt]);
        }
        #pragma unroll
        for (int nt2 = 0; nt2 < 2; nt2++) {
            uint32_t r0, r1, r2, r3;
            ldsm_x4(r0, r1, r2, r3, st + 8192 + offB[nt2]);
            bh[nt2 * 2 + 0][0] = r0; bh[nt2 * 2 + 0][1] = r2;
            bh[nt2 * 2 + 1][0] = r1; bh[nt2 * 2 + 1][1] = r3;
            if (TERMS >= 2) {
                ldsm_x4(r0, r1, r2, r3, st + 12288 + offB[nt2]);
                bl[nt2 * 2 + 0][0] = r0; bl[nt2 * 2 + 0][1] = r2;
                bl[nt2 * 2 + 1][0] = r1; bl[nt2 * 2 + 1][1] = r3;
            }
        }
        #pragma unroll
        for (int mt = 0; mt < 4; mt++)
            #pragma unroll
            for (int nt = 0; nt < 4; nt++) {
                mma_f16(acc[mt][nt], ah[mt], bh[nt]);
                if (TERMS >= 2) mma_f16(acc[mt][nt], ah[mt], bl[nt]);
                if (TERMS >= 3) mma_f16(acc[mt][nt], al[mt], bh[nt]);
            }
    }

    cp_wait<0>();
    __syncthreads();   // before smem reuse as bounce

    if (MODE == 2) {
        #pragma unroll
        for (int mt = 0; mt < 4; mt++) {
            #pragma unroll
            for (int nt = 0; nt < 4; nt++) {
                int m0 = bm * 128 + warpM * 64 + mt * 16 + (lane >> 2);
                int n0 = bn * 128 + warpN * 32 + nt * 8 + (lane & 3) * 2;
                float2 bv = *(const float2*)(bias + n0);
                float2 v0 = make_float2(acc[mt][nt][0] + bv.x, acc[mt][nt][1] + bv.y);
                float2 v1 = make_float2(acc[mt][nt][2] + bv.x, acc[mt][nt][3] + bv.y);
                *(float2*)(C + (size_t)m0 * N + n0) = v0;
                *(float2*)(C + (size_t)(m0 + 8) * N + n0) = v1;
            }
        }
    } else {
        float* bounce = (float*)smem + wid * (32 * 65);
        #pragma unroll
        for (int mt = 0; mt < 4; mt++) {
            #pragma unroll
            for (int nt = 0; nt < 4; nt++) {
                int nl = nt * 8 + (lane & 3) * 2;
                int ml = mt * 16 + (lane >> 2);
                bounce[nl * 65 + ml]            = acc[mt][nt][0];
                bounce[(nl + 1) * 65 + ml]      = acc[mt][nt][1];
                bounce[nl * 65 + ml + 8]        = acc[mt][nt][2];
                bounce[(nl + 1) * 65 + ml + 8]  = acc[mt][nt][3];
            }
        }
        __syncwarp();
        int col = bn * 128 + warpN * 32 + lane;
        float bv = bias[col];
        const float* src = bounce + lane * 65;
        if (TERMS == 1) {
            __half* dst = g_vh + (size_t)(col - 1024) * MROWS
                        + bm * 128 + warpM * 64;
            #pragma unroll
            for (int q = 0; q < 16; q++) {
                __half h[4];
                h[0] = __float2half_rn(src[q * 4 + 0] + bv);
                h[1] = __float2half_rn(src[q * 4 + 1] + bv);
                h[2] = __float2half_rn(src[q * 4 + 2] + bv);
                h[3] = __float2half_rn(src[q * 4 + 3] + bv);
                *(uint2*)(dst + q * 4) = *(uint2*)h;
            }
        } else {
            float* dst = g_qkvT + (size_t)col * MROWS + bm * 128 + warpM * 64;
            #pragma unroll
            for (int q = 0; q < 16; q++) {
                float4 v;
                v.x = src[q * 4 + 0] + bv;
                v.y = src[q * 4 + 1] + bv;
                v.z = src[q * 4 + 2] + bv;
                v.w = src[q * 4 + 3] + bv;
                ((float4*)dst)[q] = v;
            }
        }
    }
}

// ---------------------------------------------------------------------------
// Attention: fp32 FMA scores (R10), softmax -> fp16 P tile, HMMA PV phase.
// sP rows 112B stride (7x16B, conflict-free ldmatrix); sVh rows 80B stride.
// ---------------------------------------------------------------------------
__global__ __launch_bounds__(256) void attn_kernel()
{
    __shared__ float  sQT[HD * LP];
    __shared__ float  sKT[HD * LP];
    __shared__ __align__(16) __half sVh[64 * 40];   // [m][d], 80B rows
    __shared__ float  sS[LP * LP];
    __shared__ __align__(16) __half sP[64 * 56];    // [l][m] fp16, 112B rows

    int tid = threadIdx.x;
    int b2 = blockIdx.x >> 4;
    int h  = blockIdx.x & 15;

    size_t base = (size_t)b2 * WINSTRIDE + (size_t)h * SLAB;
    const float*  Qg  = g_qkvT + base;
    const float*  Kg  = g_qkvT + PARTSTRIDE + base;
    const __half* Vgh = g_vh + base;
    const __half* bm  = g_bmh + ((size_t)(b2 & 63) * NHEAD + h) * LL;

    // Load Q,K transposed to [d][l]; V fp16 into 80B-stride rows
    if (tid < 196) {
        int row = tid >> 2, ch = tid & 3;
        *(uint4*)((char*)sVh + row * 80 + ch * 16) = ((const uint4*)Vgh)[tid];
    }
    for (int t = tid; t < SLAB / 4; t += 256) {
        float4 qv = ((const float4*)Qg)[t];
        float4 kv = ((const float4*)Kg)[t];
        int j  = t * 4;
        int l2 = j >> 5;
        int d  = j & 31;
        sQT[(d + 0) * LP + l2] = qv.x;
        sQT[(d + 1) * LP + l2] = qv.y;
        sQT[(d + 2) * LP + l2] = qv.z;
        sQT[(d + 3) * LP + l2] = qv.w;
        sKT[(d + 0) * LP + l2] = kv.x;
        sKT[(d + 1) * LP + l2] = kv.y;
        sKT[(d + 2) * LP + l2] = kv.z;
        sKT[(d + 3) * LP + l2] = kv.w;
    }
    __syncthreads();

    // Scores: 13x13 grid of 4x4 tiles (fp32 FMA, proven in R10)
    if (tid < 169) {
        int lt = tid / 13, mt = tid - lt * 13;
        int l0 = lt * 4, m0 = mt * 4;
        float acc[4][4];
        #pragma unroll
        for (int i = 0; i < 4; i++)
            #pragma unroll
            for (int j = 0; j < 4; j++) acc[i][j] = 0.f;
        #pragma unroll
        for (int d = 0; d < HD; d++) {
            float4 q = *(const float4*)&sQT[d * LP + l0];
            float4 k = *(const float4*)&sKT[d * LP + m0];
            float qa[4] = {q.x, q.y, q.z, q.w};
            float ka[4] = {k.x, k.y, k.z, k.w};
            #pragma unroll
            for (int i = 0; i < 4; i++)
                #pragma unroll
                for (int j = 0; j < 4; j++)
                    acc[i][j] = fmaf(qa[i], ka[j], acc[i][j]);
        }
        #pragma unroll
        for (int i = 0; i < 4; i++) {
            int l = l0 + i;
            if (l < LTOK) {
                #pragma unroll
                for (int j = 0; j < 4; j++) {
                    int m = m0 + j;
                    if (m < LTOK)
                        sS[l * LP + m] = acc[i][j]
                            + __half2float(bm[l * LTOK + m]);
                }
            }
        }
    }
    __syncthreads();

    // Softmax per row; write P as fp16 into sP (112B-stride rows)
    {
        int warp = tid >> 5, lane = tid & 31;
        for (int row = warp; row < LTOK; row += 8) {
            float* s = sS + row * LP;
            float e0 = s[lane];
            float e1 = (lane + 32 < LTOK) ? s[lane + 32] : -CUDART_INF_F;
            float mx = fmaxf(e0, e1);
            #pragma unroll
            for (int off = 16; off; off >>= 1)
                mx = fmaxf(mx, __shfl_xor_sync(0xffffffffu, mx, off));
            float p0 = __expf(e0 - mx);
            float p1 = (lane + 32 < LTOK) ? __expf(e1 - mx) : 0.f;
            float sum = p0 + p1;
            #pragma unroll
            for (int off = 16; off; off >>= 1)
                sum += __shfl_xor_sync(0xffffffffu, sum, off);
            float inv = 1.f / sum;
            sP[row * 56 + lane] = __float2half_rn(p0 * inv);
            if (lane + 32 < LTOK)
                sP[row * 56 + lane + 32] = __float2half_rn(p1 * inv);
        }
    }
    __syncthreads();

    // PV via HMMA: O[64l x 32d] = P[64 x 49] * V[49 x 32].
    // 8 warps: mt = w>>1 (16 l rows), dh = w&1 (16 d cols).
    // k-chunks m=0..47 via mma; m=48 scalar fixup.
    {
        int w = tid >> 5, lane = tid & 31;
        int mt = w >> 1, dh = w & 1;
        uint32_t uP = smem_u32(sP), uV = smem_u32(sVh);
        uint32_t aoff = (uint32_t)(mt * 16 + (lane & 15)) * 112u
                      + (uint32_t)(lane >> 4) * 16u;
        uint32_t boff = (uint32_t)(lane & 15) * 80u
                      + (uint32_t)(lane >> 4) * 16u + (uint32_t)dh * 32u;

        float acc[2][4];
        #pragma unroll
        for (int nt = 0; nt < 2; nt++)
            #pragma unroll
            for (int q = 0; q < 4; q++) acc[nt][q] = 0.f;

        #pragma unroll
        for (int kc = 0; kc < 3; kc++) {
            uint32_t a[4];
            ldsm_x4(a[0], a[1], a[2], a[3], uP + aoff + kc * 32u);
            uint32_t r0, r1, r2, r3;
            ldsm_x4_trans(r0, r1, r2, r3, uV + boff + kc * (16u * 80u));
            uint32_t b0[2] = {r0, r1};
            uint32_t b1[2] = {r2, r3};
            mma_f16(acc[0], a, b0);
            mma_f16(acc[1], a, b1);
        }

        // fixup m=48
        int l0 = mt * 16 + (lane >> 2);
        float pA = __half2float(sP[l0 * 56 + 48]);
        float pB = __half2float(sP[(l0 + 8) * 56 + 48]);
        #pragma unroll
        for (int nt = 0; nt < 2; nt++) {
            int d = dh * 16 + nt * 8 + (lane & 3) * 2;
            float v0 = __half2float(sVh[48 * 40 + d]);
            float v1 = __half2float(sVh[48 * 40 + d + 1]);
            acc[nt][0] += pA * v0;
            acc[nt][1] += pA * v1;
            acc[nt][2] += pB * v0;
            acc[nt][3] += pB * v1;
        }

        // store (guard l < 49)
        #pragma unroll
        for (int nt = 0; nt < 2; nt++) {
            int d = dh * 16 + nt * 8 + (lane & 3) * 2;
            #pragma unroll
            for (int hf = 0; hf < 2; hf++) {
                int l = mt * 16 + (lane >> 2) + hf * 8;
                if (l < LTOK) {
                    size_t oidx = ((size_t)b2 * LTOK + l) * CDIM + h * HD + d;
                    *(__half2*)(g_ohi + oidx) =
                        __floats2half2_rn(acc[nt][hf * 2], acc[nt][hf * 2 + 1]);
                }
            }
        }
    }
}

// ---------------------------------------------------------------------------
extern "C" void kernel_launch(void* const* d_in, const int* in_sizes, int n_in,
                              void* d_out, int out_size)
{
    const float* x           = (const float*)d_in[0];
    const float* mask        = (const float*)d_in[1];
    const float* w_qkv       = (const float*)d_in[2];
    const float* b_qkv       = (const float*)d_in[3];
    const float* w_proj      = (const float*)d_in[4];
    const float* b_proj      = (const float*)d_in[5];
    const float* bias_table  = (const float*)d_in[6];
    const int*   index_table = (const int*)d_in[7];
    float* out = (float*)d_out;

    cudaFuncSetAttribute(gemm_f16x3<1, 3>, cudaFuncAttributeMaxDynamicSharedMemorySize, DYN_SMEM);
    cudaFuncSetAttribute(gemm_f16x3<1, 1>, cudaFuncAttributeMaxDynamicSharedMemorySize, DYN_SMEM);
    cudaFuncSetAttribute(gemm_f16x3<2, 1>, cudaFuncAttributeMaxDynamicSharedMemorySize, DYN_SMEM);

    // 0) weight transpose+split, x split, fused bias+mask table (fp16)
    wtrans_kernel<1><<<dim3(NQKV / 32, KDIM / 32), dim3(32, 8)>>>(w_qkv, KDIM, NQKV);
    wtrans_kernel<2><<<dim3(CDIM / 32, KDIM / 32), dim3(32, 8)>>>(w_proj, KDIM, CDIM);
    split_x_kernel<<<((size_t)MROWS * CDIM) / 4 / 256, 256>>>(x);
    biasmask_kernel<<<64 * NHEAD, 256>>>(mask, bias_table, index_table);

    // 1a) QK columns (0..1023): 3-term fp32 scatter
    gemm_f16x3<1, 3><<<dim3(8, MROWS / 128), 256, DYN_SMEM>>>(b_qkv, nullptr, NQKV, 0);
    // 1b) V columns (1024..1535): 1-term fp16 scatter
    gemm_f16x3<1, 1><<<dim3(4, MROWS / 128), 256, DYN_SMEM>>>(b_qkv, nullptr, NQKV, 8);

    // 2) fused window attention (FMA scores + HMMA PV)
    attn_kernel<<<BNW * NHEAD, 256>>>();

    // 3) projection GEMM: 1-term
    gemm_f16x3<2, 1><<<dim3(4, MROWS / 128), 256, DYN_SMEM>>>(b_proj, out, CDIM, 0);
}

// round 13
// speedup vs baseline: 1.1465x; 1.0932x over previous
#include <cuda_runtime.h>
#include <cuda_fp16.h>
#include <cstdint>
#include <math_constants.h>

// Problem constants
#define CDIM 512
#define NHEAD 16
#define HD 32
#define LTOK 49
#define BNW 4096
#define MROWS (BNW * LTOK)            // 200704
#define NQKV (3 * CDIM)               // 1536
#define SLAB (LTOK * HD)              // 1568
#define WINSTRIDE (NHEAD * SLAB)      // 25088
#define PARTSTRIDE ((size_t)CDIM * MROWS)
#define KDIM 512
#define KITER (KDIM / 16)             // 32 iters of K=16
#define LP 52                          // padded token dim
#define LL (LTOK * LTOK)               // 2401

// Scratch (device globals — no allocation)
__device__ float  g_qkvT[(size_t)1024 * MROWS];     // Q,K channel-major fp32
__device__ __half g_vh[(size_t)CDIM * MROWS];       // V channel-major fp16
__device__ __half g_xhi[(size_t)MROWS * CDIM];      // x split hi/lo
__device__ __half g_xlo[(size_t)MROWS * CDIM];
__device__ __half g_ohi[(size_t)MROWS * CDIM];      // attn out, fp16 (hi only)
__device__ __half g_whi1[(size_t)NQKV * KDIM];      // w_qkv^T hi/lo [N][K]
__device__ __half g_wlo1[(size_t)NQKV * KDIM];
__device__ __half g_whi2[(size_t)CDIM * KDIM];      // w_proj^T hi (1-term)
__device__ __half g_wlo2[(size_t)CDIM * KDIM];
__device__ __half g_bmh[64 * NHEAD * LL];           // fused bias+mask, fp16

// ---------------------------------------------------------------------------
// PTX helpers (sm_80-era ISA — tcgen05 unavailable at compute_103)
// ---------------------------------------------------------------------------
__device__ __forceinline__ uint32_t smem_u32(const void* p) {
    uint32_t a;
    asm("{ .reg .u64 t; cvta.to.shared.u64 t, %1; cvt.u32.u64 %0, t; }"
        : "=r"(a) : "l"(p));
    return a;
}
__device__ __forceinline__ void cp_async16(uint32_t smem, const void* g) {
    asm volatile("cp.async.cg.shared.global [%0], [%1], 16;"
                 :: "r"(smem), "l"(g) : "memory");
}
__device__ __forceinline__ void cp_commit() {
    asm volatile("cp.async.commit_group;" ::: "memory");
}
template <int N>
__device__ __forceinline__ void cp_wait() {
    asm volatile("cp.async.wait_group %0;" :: "n"(N) : "memory");
}
__device__ __forceinline__ void ldsm_x4(uint32_t& r0, uint32_t& r1,
                                        uint32_t& r2, uint32_t& r3,
                                        uint32_t addr) {
    asm volatile("ldmatrix.sync.aligned.m8n8.x4.shared.b16 {%0,%1,%2,%3}, [%4];"
                 : "=r"(r0), "=r"(r1), "=r"(r2), "=r"(r3) : "r"(addr));
}
__device__ __forceinline__ void ldsm_x4_trans(uint32_t& r0, uint32_t& r1,
                                              uint32_t& r2, uint32_t& r3,
                                              uint32_t addr) {
    asm volatile("ldmatrix.sync.aligned.m8n8.x4.trans.shared.b16 {%0,%1,%2,%3}, [%4];"
                 : "=r"(r0), "=r"(r1), "=r"(r2), "=r"(r3) : "r"(addr));
}
__device__ __forceinline__ void mma_f16(float* d, const uint32_t* a,
                                        const uint32_t* b) {
    asm volatile(
        "mma.sync.aligned.m16n8k16.row.col.f32.f16.f16.f32 "
        "{%0,%1,%2,%3}, {%4,%5,%6,%7}, {%8,%9}, {%0,%1,%2,%3};"
        : "+f"(d[0]), "+f"(d[1]), "+f"(d[2]), "+f"(d[3])
        : "r"(a[0]), "r"(a[1]), "r"(a[2]), "r"(a[3]), "r"(b[0]), "r"(b[1]));
}

#define STAGE_BYTES 16384
#define NSTAGE 4
#define DYN_SMEM 66560   // max(4*16384, 8 warps * 32*65*4 bounce)

__device__ __forceinline__ uint32_t sw16(int row, int c) {
    return (uint32_t)row * 32u + (uint32_t)((c ^ ((row >> 2) & 1)) << 4);
}

// ---------------------------------------------------------------------------
// x -> hi/lo fp16 split (elementwise)
// ---------------------------------------------------------------------------
__global__ __launch_bounds__(256) void split_x_kernel(const float* __restrict__ src) {
    size_t i = ((size_t)blockIdx.x * 256 + threadIdx.x) * 4;
    float4 v = *(const float4*)(src + i);
    __half h0 = __float2half_rn(v.x), h1 = __float2half_rn(v.y);
    __half h2 = __float2half_rn(v.z), h3 = __float2half_rn(v.w);
    __half l0 = __float2half_rn(v.x - __half2float(h0));
    __half l1 = __float2half_rn(v.y - __half2float(h1));
    __half l2 = __float2half_rn(v.z - __half2float(h2));
    __half l3 = __float2half_rn(v.w - __half2float(h3));
    __half2 hh[2] = {__halves2half2(h0, h1), __halves2half2(h2, h3)};
    __half2 ll[2] = {__halves2half2(l0, l1), __halves2half2(l2, l3)};
    *(uint2*)(g_xhi + i) = *(uint2*)hh;
    *(uint2*)(g_xlo + i) = *(uint2*)ll;
}

// ---------------------------------------------------------------------------
// Weight transpose + split: src[k*N + n] -> dst_{hi,lo}[n*K + k]
// ---------------------------------------------------------------------------
template <int SEL>
__global__ void wtrans_kernel(const float* __restrict__ src, int K, int N) {
    __half* dhi = (SEL == 1) ? g_whi1 : g_whi2;
    __half* dlo = (SEL == 1) ? g_wlo1 : g_wlo2;
    __shared__ float t[32][33];
    int n0 = blockIdx.x * 32, k0 = blockIdx.y * 32;
    int x = threadIdx.x, y = threadIdx.y;
    #pragma unroll
    for (int i = y; i < 32; i += 8)
        t[i][x] = src[(size_t)(k0 + i) * N + n0 + x];
    __syncthreads();
    #pragma unroll
    for (int i = y; i < 32; i += 8) {
        float v = t[x][i];
        __half h = __float2half_rn(v);
        __half l = __float2half_rn(v - __half2float(h));
        dhi[(size_t)(n0 + i) * K + k0 + x] = h;
        dlo[(size_t)(n0 + i) * K + k0 + x] = l;
    }
}

// ---------------------------------------------------------------------------
// Fused bias+mask precompute (fp16 output)
// ---------------------------------------------------------------------------
__global__ __launch_bounds__(256) void biasmask_kernel(
    const float* __restrict__ mask,
    const float* __restrict__ bias_table,
    const int*   __restrict__ index_table)
{
    int wh = blockIdx.x;
    int w = wh >> 4, h = wh & 15;
    const float* mrow = mask + (size_t)w * LL;
    __half* dst = g_bmh + (size_t)wh * LL;
    for (int o = threadIdx.x; o < LL; o += 256)
        dst[o] = __float2half_rn(bias_table[index_table[o] * NHEAD + h] + mrow[o]);
}

// ---------------------------------------------------------------------------
// fp16 split GEMM, variable term count (256 thr, 2x4 warps, 64x32 warp tile).
// TERMS=3 MODE=1: QK columns -> fp32 scatter to g_qkvT
// TERMS=1 MODE=1: V columns  -> fp16 scatter to g_vh
// TERMS=1 MODE=2: proj       -> row-major fp32 to C
// ---------------------------------------------------------------------------
template <int MODE, int TERMS>
__global__ __launch_bounds__(256) void gemm_f16x3(
    const float* __restrict__ bias, float* __restrict__ C, int N, int bnOff)
{
    extern __shared__ char smem[];
    const __half* Ahi = (MODE == 1) ? g_xhi : g_ohi;
    const __half* Alo = (MODE == 1) ? g_xlo : g_ohi;   // dummy when TERMS<3
    const __half* Bhi = (MODE == 1) ? g_whi1 : g_whi2;
    const __half* Blo = (MODE == 1) ? g_wlo1 : g_wlo2;

    const int tid = threadIdx.x;
    const int lane = tid & 31, wid = tid >> 5;
    const int warpM = wid & 1, warpN = wid >> 1;   // 2 x 4 warps, 64x32 tiles
    const int bm = blockIdx.y, bn = blockIdx.x + bnOff;
    const uint32_t sbase = smem_u32(smem);

    const int grow = tid >> 1, gch = tid & 1;
    const uint32_t soff = sw16(grow, gch);
    const __half* gAhi = Ahi + (size_t)(bm * 128 + grow) * KDIM + gch * 8;
    const __half* gAlo = Alo + (size_t)(bm * 128 + grow) * KDIM + gch * 8;
    const __half* gBhi = Bhi + (size_t)(bn * 128 + grow) * KDIM + gch * 8;
    const __half* gBlo = Blo + (size_t)(bn * 128 + grow) * KDIM + gch * 8;

    float acc[4][4][4];
    #pragma unroll
    for (int i = 0; i < 4; i++)
        #pragma unroll
        for (int j = 0; j < 4; j++)
            #pragma unroll
            for (int q = 0; q < 4; q++) acc[i][j][q] = 0.f;

    #pragma unroll
    for (int s = 0; s < NSTAGE - 1; s++) {
        uint32_t st = sbase + s * STAGE_BYTES;
        int k0 = s * 16;
        cp_async16(st + soff, gAhi + k0);
        if (TERMS >= 3) cp_async16(st + 4096 + soff, gAlo + k0);
        cp_async16(st + 8192 + soff, gBhi + k0);
        if (TERMS >= 2) cp_async16(st + 12288 + soff, gBlo + k0);
        cp_commit();
    }

    const int lrow = lane & 15, lhalf = lane >> 4;
    uint32_t offA[4], offB[2];
    #pragma unroll
    for (int mt = 0; mt < 4; mt++)
        offA[mt] = sw16(warpM * 64 + mt * 16 + lrow, lhalf);
    #pragma unroll
    for (int nt2 = 0; nt2 < 2; nt2++)
        offB[nt2] = sw16(warpN * 32 + nt2 * 16 + lrow, lhalf);

    for (int it = 0; it < KITER; it++) {
        cp_wait<NSTAGE - 2>();
        __syncthreads();

        if (it + NSTAGE - 1 < KITER) {
            int s = (it + NSTAGE - 1) % NSTAGE;
            uint32_t st = sbase + s * STAGE_BYTES;
            int k0 = (it + NSTAGE - 1) * 16;
            cp_async16(st + soff, gAhi + k0);
            if (TERMS >= 3) cp_async16(st + 4096 + soff, gAlo + k0);
            cp_async16(st + 8192 + soff, gBhi + k0);
            if (TERMS >= 2) cp_async16(st + 12288 + soff, gBlo + k0);
        }
        cp_commit();

        const uint32_t st = sbase + (it % NSTAGE) * STAGE_BYTES;

        uint32_t ah[4][4], al[4][4], bh[4][2], bl[4][2];
        #pragma unroll
        for (int mt = 0; mt < 4; mt++) {
            ldsm_x4(ah[mt][0], ah[mt][1], ah[mt][2], ah[mt][3], st + offA[mt]);
            if (TERMS >= 3)
                ldsm_x4(al[mt][0], al[mt][1], al[mt][2], al[mt][3],
                        st + 4096 + offA[mt]);
        }
        #pragma unroll
        for (int nt2 = 0; nt2 < 2; nt2++) {
            uint32_t r0, r1, r2, r3;
            ldsm_x4(r0, r1, r2, r3, st + 8192 + offB[nt2]);
            bh[nt2 * 2 + 0][0] = r0; bh[nt2 * 2 + 0][1] = r2;
            bh[nt2 * 2 + 1][0] = r1; bh[nt2 * 2 + 1][1] = r3;
            if (TERMS >= 2) {
                ldsm_x4(r0, r1, r2, r3, st + 12288 + offB[nt2]);
                bl[nt2 * 2 + 0][0] = r0; bl[nt2 * 2 + 0][1] = r2;
                bl[nt2 * 2 + 1][0] = r1; bl[nt2 * 2 + 1][1] = r3;
            }
        }
        #pragma unroll
        for (int mt = 0; mt < 4; mt++)
            #pragma unroll
            for (int nt = 0; nt < 4; nt++) {
                mma_f16(acc[mt][nt], ah[mt], bh[nt]);
                if (TERMS >= 2) mma_f16(acc[mt][nt], ah[mt], bl[nt]);
                if (TERMS >= 3) mma_f16(acc[mt][nt], al[mt], bh[nt]);
            }
    }

    cp_wait<0>();
    __syncthreads();   // before smem reuse as bounce

    if (MODE == 2) {
        #pragma unroll
        for (int mt = 0; mt < 4; mt++) {
            #pragma unroll
            for (int nt = 0; nt < 4; nt++) {
                int m0 = bm * 128 + warpM * 64 + mt * 16 + (lane >> 2);
                int n0 = bn * 128 + warpN * 32 + nt * 8 + (lane & 3) * 2;
                float2 bv = *(const float2*)(bias + n0);
                float2 v0 = make_float2(acc[mt][nt][0] + bv.x, acc[mt][nt][1] + bv.y);
                float2 v1 = make_float2(acc[mt][nt][2] + bv.x, acc[mt][nt][3] + bv.y);
                *(float2*)(C + (size_t)m0 * N + n0) = v0;
                *(float2*)(C + (size_t)(m0 + 8) * N + n0) = v1;
            }
        }
    } else {
        float* bounce = (float*)smem + wid * (32 * 65);
        #pragma unroll
        for (int mt = 0; mt < 4; mt++) {
            #pragma unroll
            for (int nt = 0; nt < 4; nt++) {
                int nl = nt * 8 + (lane & 3) * 2;
                int ml = mt * 16 + (lane >> 2);
                bounce[nl * 65 + ml]            = acc[mt][nt][0];
                bounce[(nl + 1) * 65 + ml]      = acc[mt][nt][1];
                bounce[nl * 65 + ml + 8]        = acc[mt][nt][2];
                bounce[(nl + 1) * 65 + ml + 8]  = acc[mt][nt][3];
            }
        }
        __syncwarp();
        int col = bn * 128 + warpN * 32 + lane;
        float bv = bias[col];
        const float* src = bounce + lane * 65;
        if (TERMS == 1) {
            __half* dst = g_vh + (size_t)(col - 1024) * MROWS
                        + bm * 128 + warpM * 64;
            #pragma unroll
            for (int q = 0; q < 16; q++) {
                __half h[4];
                h[0] = __float2half_rn(src[q * 4 + 0] + bv);
                h[1] = __float2half_rn(src[q * 4 + 1] + bv);
                h[2] = __float2half_rn(src[q * 4 + 2] + bv);
                h[3] = __float2half_rn(src[q * 4 + 3] + bv);
                *(uint2*)(dst + q * 4) = *(uint2*)h;
            }
        } else {
            float* dst = g_qkvT + (size_t)col * MROWS + bm * 128 + warpM * 64;
            #pragma unroll
            for (int q = 0; q < 16; q++) {
                float4 v;
                v.x = src[q * 4 + 0] + bv;
                v.y = src[q * 4 + 1] + bv;
                v.z = src[q * 4 + 2] + bv;
                v.w = src[q * 4 + 3] + bv;
                ((float4*)dst)[q] = v;
            }
        }
    }
}

// ---------------------------------------------------------------------------
// Attention: in-kernel Q/K hi-lo split -> HMMA 3-term scores -> softmax ->
// fp16 P -> HMMA PV. All operand tiles natural [token][d] layout, 80B rows.
// ---------------------------------------------------------------------------
__global__ __launch_bounds__(256) void attn_kernel()
{
    __shared__ __align__(16) __half sQh[64 * 40];   // [l][d], 80B rows
    __shared__ __align__(16) __half sQl[64 * 40];
    __shared__ __align__(16) __half sKh[64 * 40];
    __shared__ __align__(16) __half sKl[64 * 40];
    __shared__ __align__(16) __half sVh[64 * 40];
    __shared__ float sS[LP * LP];
    __shared__ __align__(16) __half sP[64 * 56];    // [l][m], 112B rows

    int tid = threadIdx.x;
    int b2 = blockIdx.x >> 4;
    int h  = blockIdx.x & 15;

    size_t base = (size_t)b2 * WINSTRIDE + (size_t)h * SLAB;
    const float*  Qg  = g_qkvT + base;
    const float*  Kg  = g_qkvT + PARTSTRIDE + base;
    const __half* Vgh = g_vh + base;
    const __half* bm  = g_bmh + ((size_t)(b2 & 63) * NHEAD + h) * LL;

    // V: 196 uint4 into 80B-stride rows
    if (tid < 196) {
        int row = tid >> 2, ch = tid & 3;
        *(uint4*)((char*)sVh + row * 80 + ch * 16) = ((const uint4*)Vgh)[tid];
    }
    // Q,K: load fp32, split hi/lo in registers, store fp16 planes (no transpose)
    for (int t = tid; t < SLAB / 4; t += 256) {
        float4 qv = ((const float4*)Qg)[t];
        float4 kv = ((const float4*)Kg)[t];
        int l = t >> 3;
        int doff = (t & 7) * 8;     // byte offset within 64B row payload
        float qa[4] = {qv.x, qv.y, qv.z, qv.w};
        float ka[4] = {kv.x, kv.y, kv.z, kv.w};
        __half qh[4], ql[4], kh[4], kl[4];
        #pragma unroll
        for (int j = 0; j < 4; j++) {
            qh[j] = __float2half_rn(qa[j]);
            ql[j] = __float2half_rn(qa[j] - __half2float(qh[j]));
            kh[j] = __float2half_rn(ka[j]);
            kl[j] = __float2half_rn(ka[j] - __half2float(kh[j]));
        }
        uint32_t d = (uint32_t)l * 80u + (uint32_t)doff;
        *(uint2*)((char*)sQh + d) = *(uint2*)qh;
        *(uint2*)((char*)sQl + d) = *(uint2*)ql;
        *(uint2*)((char*)sKh + d) = *(uint2*)kh;
        *(uint2*)((char*)sKl + d) = *(uint2*)kl;
    }
    __syncthreads();

    // Scores via HMMA: warp w -> m-tile (w>>1, 16 rows), n-half (w&1, 32 cols)
    {
        int w = tid >> 5, lane = tid & 31;
        int mt = w >> 1, nh = w & 1;
        uint32_t uQh = smem_u32(sQh), uQl = smem_u32(sQl);
        uint32_t uKh = smem_u32(sKh), uKl = smem_u32(sKl);
        uint32_t aoff  = (uint32_t)(mt * 16 + (lane & 15)) * 80u
                       + (uint32_t)(lane >> 4) * 16u;
        uint32_t boff0 = (uint32_t)(nh * 32 + (lane & 15)) * 80u
                       + (uint32_t)(lane >> 4) * 16u;
        uint32_t boff1 = boff0 + 16u * 80u;

        float acc[4][4];
        #pragma unroll
        for (int i = 0; i < 4; i++)
            #pragma unroll
            for (int j = 0; j < 4; j++) acc[i][j] = 0.f;

        #pragma unroll
        for (int ks = 0; ks < 2; ks++) {
            uint32_t kb = ks * 32u;
            uint32_t qh[4], ql[4], kh[4][2], kl[4][2];
            ldsm_x4(qh[0], qh[1], qh[2], qh[3], uQh + aoff + kb);
            ldsm_x4(ql[0], ql[1], ql[2], ql[3], uQl + aoff + kb);
            uint32_t r0, r1, r2, r3;
            ldsm_x4(r0, r1, r2, r3, uKh + boff0 + kb);
            kh[0][0] = r0; kh[0][1] = r2; kh[1][0] = r1; kh[1][1] = r3;
            ldsm_x4(r0, r1, r2, r3, uKh + boff1 + kb);
            kh[2][0] = r0; kh[2][1] = r2; kh[3][0] = r1; kh[3][1] = r3;
            ldsm_x4(r0, r1, r2, r3, uKl + boff0 + kb);
            kl[0][0] = r0; kl[0][1] = r2; kl[1][0] = r1; kl[1][1] = r3;
            ldsm_x4(r0, r1, r2, r3, uKl + boff1 + kb);
            kl[2][0] = r0; kl[2][1] = r2; kl[3][0] = r1; kl[3][1] = r3;
            #pragma unroll
            for (int nt = 0; nt < 4; nt++) {
                mma_f16(acc[nt], qh, kh[nt]);
                mma_f16(acc[nt], qh, kl[nt]);
                mma_f16(acc[nt], ql, kh[nt]);
            }
        }

        // store S + bias+mask (discard padded rows/cols)
        int rbase = mt * 16 + (lane >> 2);
        #pragma unroll
        for (int nt = 0; nt < 4; nt++) {
            int c = nh * 32 + nt * 8 + (lane & 3) * 2;
            #pragma unroll
            for (int hf = 0; hf < 2; hf++) {
                int r = rbase + hf * 8;
                if (r < LTOK) {
                    if (c < LTOK)
                        sS[r * LP + c] = acc[nt][hf * 2 + 0]
                            + __half2float(bm[r * LTOK + c]);
                    if (c + 1 < LTOK)
                        sS[r * LP + c + 1] = acc[nt][hf * 2 + 1]
                            + __half2float(bm[r * LTOK + c + 1]);
                }
            }
        }
    }
    __syncthreads();

    // Softmax per row; write P as fp16 into sP (112B-stride rows)
    {
        int warp = tid >> 5, lane = tid & 31;
        for (int row = warp; row < LTOK; row += 8) {
            float* s = sS + row * LP;
            float e0 = s[lane];
            float e1 = (lane + 32 < LTOK) ? s[lane + 32] : -CUDART_INF_F;
            float mx = fmaxf(e0, e1);
            #pragma unroll
            for (int off = 16; off; off >>= 1)
                mx = fmaxf(mx, __shfl_xor_sync(0xffffffffu, mx, off));
            float p0 = __expf(e0 - mx);
            float p1 = (lane + 32 < LTOK) ? __expf(e1 - mx) : 0.f;
            float sum = p0 + p1;
            #pragma unroll
            for (int off = 16; off; off >>= 1)
                sum += __shfl_xor_sync(0xffffffffu, sum, off);
            float inv = 1.f / sum;
            sP[row * 56 + lane] = __float2half_rn(p0 * inv);
            if (lane + 32 < LTOK)
                sP[row * 56 + lane + 32] = __float2half_rn(p1 * inv);
        }
    }
    __syncthreads();

    // PV via HMMA: O[64l x 32d] = P[64 x 49] * V[49 x 32]  (verified R12)
    {
        int w = tid >> 5, lane = tid & 31;
        int mt = w >> 1, dh = w & 1;
        uint32_t uP = smem_u32(sP), uV = smem_u32(sVh);
        uint32_t aoff = (uint32_t)(mt * 16 + (lane & 15)) * 112u
                      + (uint32_t)(lane >> 4) * 16u;
        uint32_t boff = (uint32_t)(lane & 15) * 80u
                      + (uint32_t)(lane >> 4) * 16u + (uint32_t)dh * 32u;

        float acc[2][4];
        #pragma unroll
        for (int nt = 0; nt < 2; nt++)
            #pragma unroll
            for (int q = 0; q < 4; q++) acc[nt][q] = 0.f;

        #pragma unroll
        for (int kc = 0; kc < 3; kc++) {
            uint32_t a[4];
            ldsm_x4(a[0], a[1], a[2], a[3], uP + aoff + kc * 32u);
            uint32_t r0, r1, r2, r3;
            ldsm_x4_trans(r0, r1, r2, r3, uV + boff + kc * (16u * 80u));
            uint32_t b0[2] = {r0, r1};
            uint32_t b1[2] = {r2, r3};
            mma_f16(acc[0], a, b0);
            mma_f16(acc[1], a, b1);
        }

        // fixup m=48
        int l0 = mt * 16 + (lane >> 2);
        float pA = __half2float(sP[l0 * 56 + 48]);
        float pB = __half2float(sP[(l0 + 8) * 56 + 48]);
        #pragma unroll
        for (int nt = 0; nt < 2; nt++) {
            int d = dh * 16 + nt * 8 + (lane & 3) * 2;
            float v0 = __half2float(sVh[48 * 40 + d]);
            float v1 = __half2float(sVh[48 * 40 + d + 1]);
            acc[nt][0] += pA * v0;
            acc[nt][1] += pA * v1;
            acc[nt][2] += pB * v0;
            acc[nt][3] += pB * v1;
        }

        // store (guard l < 49)
        #pragma unroll
        for (int nt = 0; nt < 2; nt++) {
            int d = dh * 16 + nt * 8 + (lane & 3) * 2;
            #pragma unroll
            for (int hf = 0; hf < 2; hf++) {
                int l = mt * 16 + (lane >> 2) + hf * 8;
                if (l < LTOK) {
                    size_t oidx = ((size_t)b2 * LTOK + l) * CDIM + h * HD + d;
                    *(__half2*)(g_ohi + oidx) =
                        __floats2half2_rn(acc[nt][hf * 2], acc[nt][hf * 2 + 1]);
                }
            }
        }
    }
}

// ---------------------------------------------------------------------------
extern "C" void kernel_launch(void* const* d_in, const int* in_sizes, int n_in,
                              void* d_out, int out_size)
{
    const float* x           = (const float*)d_in[0];
    const float* mask        = (const float*)d_in[1];
    const float* w_qkv       = (const float*)d_in[2];
    const float* b_qkv       = (const float*)d_in[3];
    const float* w_proj      = (const float*)d_in[4];
    const float* b_proj      = (const float*)d_in[5];
    const float* bias_table  = (const float*)d_in[6];
    const int*   index_table = (const int*)d_in[7];
    float* out = (float*)d_out;

    cudaFuncSetAttribute(gemm_f16x3<1, 3>, cudaFuncAttributeMaxDynamicSharedMemorySize, DYN_SMEM);
    cudaFuncSetAttribute(gemm_f16x3<1, 1>, cudaFuncAttributeMaxDynamicSharedMemorySize, DYN_SMEM);
    cudaFuncSetAttribute(gemm_f16x3<2, 1>, cudaFuncAttributeMaxDynamicSharedMemorySize, DYN_SMEM);

    // 0) weight transpose+split, x split, fused bias+mask table (fp16)
    wtrans_kernel<1><<<dim3(NQKV / 32, KDIM / 32), dim3(32, 8)>>>(w_qkv, KDIM, NQKV);
    wtrans_kernel<2><<<dim3(CDIM / 32, KDIM / 32), dim3(32, 8)>>>(w_proj, KDIM, CDIM);
    split_x_kernel<<<((size_t)MROWS * CDIM) / 4 / 256, 256>>>(x);
    biasmask_kernel<<<64 * NHEAD, 256>>>(mask, bias_table, index_table);

    // 1a) QK columns (0..1023): 3-term fp32 scatter (16B granules)
    gemm_f16x3<1, 3><<<dim3(8, MROWS / 128), 256, DYN_SMEM>>>(b_qkv, nullptr, NQKV, 0);
    // 1b) V columns (1024..1535): 1-term fp16 scatter
    gemm_f16x3<1, 1><<<dim3(4, MROWS / 128), 256, DYN_SMEM>>>(b_qkv, nullptr, NQKV, 8);

    // 2) fused window attention (in-kernel split + HMMA scores + HMMA PV)
    attn_kernel<<<BNW * NHEAD, 256>>>();

    // 3) projection GEMM: 1-term
    gemm_f16x3<2, 1><<<dim3(4, MROWS / 128), 256, DYN_SMEM>>>(b_proj, out, CDIM, 0);
}

// round 14
// speedup vs baseline: 1.2091x; 1.0546x over previous
#include <cuda_runtime.h>
#include <cuda_fp16.h>
#include <cstdint>
#include <math_constants.h>

// Problem constants
#define CDIM 512
#define NHEAD 16
#define HD 32
#define LTOK 49
#define BNW 4096
#define MROWS (BNW * LTOK)            // 200704
#define NQKV (3 * CDIM)               // 1536
#define SLAB (LTOK * HD)              // 1568
#define WINSTRIDE (NHEAD * SLAB)      // 25088
#define PARTSTRIDE ((size_t)CDIM * MROWS)
#define KDIM 512
#define KITER (KDIM / 16)             // 32 iters of K=16
#define LP 52                          // padded token dim
#define LL (LTOK * LTOK)               // 2401

// Scratch (device globals — no allocation)
__device__ float  g_qkvT[(size_t)1024 * MROWS];     // Q,K channel-major fp32
__device__ __half g_vh[(size_t)CDIM * MROWS];       // V channel-major fp16
__device__ __half g_xhi[(size_t)MROWS * CDIM];      // x split hi/lo
__device__ __half g_xlo[(size_t)MROWS * CDIM];
__device__ __half g_ohi[(size_t)MROWS * CDIM];      // attn out, fp16 (hi only)
__device__ __half g_whi1[(size_t)NQKV * KDIM];      // w_qkv^T hi/lo [N][K]
__device__ __half g_wlo1[(size_t)NQKV * KDIM];
__device__ __half g_whi2[(size_t)CDIM * KDIM];      // w_proj^T hi (1-term)
__device__ __half g_wlo2[(size_t)CDIM * KDIM];
__device__ __half g_bmh[64 * NHEAD * LL];           // fused bias+mask, fp16

// ---------------------------------------------------------------------------
// PTX helpers (sm_80-era ISA — tcgen05 unavailable at compute_103)
// ---------------------------------------------------------------------------
__device__ __forceinline__ uint32_t smem_u32(const void* p) {
    uint32_t a;
    asm("{ .reg .u64 t; cvta.to.shared.u64 t, %1; cvt.u32.u64 %0, t; }"
        : "=r"(a) : "l"(p));
    return a;
}
__device__ __forceinline__ void cp_async16(uint32_t smem, const void* g) {
    asm volatile("cp.async.cg.shared.global [%0], [%1], 16;"
                 :: "r"(smem), "l"(g) : "memory");
}
__device__ __forceinline__ void cp_commit() {
    asm volatile("cp.async.commit_group;" ::: "memory");
}
template <int N>
__device__ __forceinline__ void cp_wait() {
    asm volatile("cp.async.wait_group %0;" :: "n"(N) : "memory");
}
__device__ __forceinline__ void ldsm_x4(uint32_t& r0, uint32_t& r1,
                                        uint32_t& r2, uint32_t& r3,
                                        uint32_t addr) {
    asm volatile("ldmatrix.sync.aligned.m8n8.x4.shared.b16 {%0,%1,%2,%3}, [%4];"
                 : "=r"(r0), "=r"(r1), "=r"(r2), "=r"(r3) : "r"(addr));
}
__device__ __forceinline__ void ldsm_x4_trans(uint32_t& r0, uint32_t& r1,
                                              uint32_t& r2, uint32_t& r3,
                                              uint32_t addr) {
    asm volatile("ldmatrix.sync.aligned.m8n8.x4.trans.shared.b16 {%0,%1,%2,%3}, [%4];"
                 : "=r"(r0), "=r"(r1), "=r"(r2), "=r"(r3) : "r"(addr));
}
__device__ __forceinline__ void mma_f16(float* d, const uint32_t* a,
                                        const uint32_t* b) {
    asm volatile(
        "mma.sync.aligned.m16n8k16.row.col.f32.f16.f16.f32 "
        "{%0,%1,%2,%3}, {%4,%5,%6,%7}, {%8,%9}, {%0,%1,%2,%3};"
        : "+f"(d[0]), "+f"(d[1]), "+f"(d[2]), "+f"(d[3])
        : "r"(a[0]), "r"(a[1]), "r"(a[2]), "r"(a[3]), "r"(b[0]), "r"(b[1]));
}

#define STAGE_BYTES 16384
#define NSTAGE 4
#define DYN_SMEM 66560   // max(4*16384, 8 warps * 32*65*4 bounce)

__device__ __forceinline__ uint32_t sw16(int row, int c) {
    return (uint32_t)row * 32u + (uint32_t)((c ^ ((row >> 2) & 1)) << 4);
}

// ---------------------------------------------------------------------------
// x -> hi/lo fp16 split (elementwise)
// ---------------------------------------------------------------------------
__global__ __launch_bounds__(256) void split_x_kernel(const float* __restrict__ src) {
    size_t i = ((size_t)blockIdx.x * 256 + threadIdx.x) * 4;
    float4 v = *(const float4*)(src + i);
    __half h0 = __float2half_rn(v.x), h1 = __float2half_rn(v.y);
    __half h2 = __float2half_rn(v.z), h3 = __float2half_rn(v.w);
    __half l0 = __float2half_rn(v.x - __half2float(h0));
    __half l1 = __float2half_rn(v.y - __half2float(h1));
    __half l2 = __float2half_rn(v.z - __half2float(h2));
    __half l3 = __float2half_rn(v.w - __half2float(h3));
    __half2 hh[2] = {__halves2half2(h0, h1), __halves2half2(h2, h3)};
    __half2 ll[2] = {__halves2half2(l0, l1), __halves2half2(l2, l3)};
    *(uint2*)(g_xhi + i) = *(uint2*)hh;
    *(uint2*)(g_xlo + i) = *(uint2*)ll;
}

// ---------------------------------------------------------------------------
// Weight transpose + split: src[k*N + n] -> dst_{hi,lo}[n*K + k]
// ---------------------------------------------------------------------------
template <int SEL>
__global__ void wtrans_kernel(const float* __restrict__ src, int K, int N) {
    __half* dhi = (SEL == 1) ? g_whi1 : g_whi2;
    __half* dlo = (SEL == 1) ? g_wlo1 : g_wlo2;
    __shared__ float t[32][33];
    int n0 = blockIdx.x * 32, k0 = blockIdx.y * 32;
    int x = threadIdx.x, y = threadIdx.y;
    #pragma unroll
    for (int i = y; i < 32; i += 8)
        t[i][x] = src[(size_t)(k0 + i) * N + n0 + x];
    __syncthreads();
    #pragma unroll
    for (int i = y; i < 32; i += 8) {
        float v = t[x][i];
        __half h = __float2half_rn(v);
        __half l = __float2half_rn(v - __half2float(h));
        dhi[(size_t)(n0 + i) * K + k0 + x] = h;
        dlo[(size_t)(n0 + i) * K + k0 + x] = l;
    }
}

// ---------------------------------------------------------------------------
// Fused bias+mask precompute (fp16 output)
// ---------------------------------------------------------------------------
__global__ __launch_bounds__(256) void biasmask_kernel(
    const float* __restrict__ mask,
    const float* __restrict__ bias_table,
    const int*   __restrict__ index_table)
{
    int wh = blockIdx.x;
    int w = wh >> 4, h = wh & 15;
    const float* mrow = mask + (size_t)w * LL;
    __half* dst = g_bmh + (size_t)wh * LL;
    for (int o = threadIdx.x; o < LL; o += 256)
        dst[o] = __float2half_rn(bias_table[index_table[o] * NHEAD + h] + mrow[o]);
}

// ---------------------------------------------------------------------------
// fp16 split GEMM, variable term count (256 thr, 2x4 warps, 64x32 warp tile).
// TERMS=3 MODE=1: QK columns -> fp32 scatter to g_qkvT
// TERMS=1 MODE=1: V columns  -> fp16 scatter to g_vh
// TERMS=1 MODE=2: proj       -> row-major fp32 to C
// ---------------------------------------------------------------------------
template <int MODE, int TERMS>
__global__ __launch_bounds__(256) void gemm_f16x3(
    const float* __restrict__ bias, float* __restrict__ C, int N, int bnOff)
{
    extern __shared__ char smem[];
    const __half* Ahi = (MODE == 1) ? g_xhi : g_ohi;
    const __half* Alo = (MODE == 1) ? g_xlo : g_ohi;   // dummy when TERMS<3
    const __half* Bhi = (MODE == 1) ? g_whi1 : g_whi2;
    const __half* Blo = (MODE == 1) ? g_wlo1 : g_wlo2;

    const int tid = threadIdx.x;
    const int lane = tid & 31, wid = tid >> 5;
    const int warpM = wid & 1, warpN = wid >> 1;   // 2 x 4 warps, 64x32 tiles
    const int bm = blockIdx.y, bn = blockIdx.x + bnOff;
    const uint32_t sbase = smem_u32(smem);

    const int grow = tid >> 1, gch = tid & 1;
    const uint32_t soff = sw16(grow, gch);
    const __half* gAhi = Ahi + (size_t)(bm * 128 + grow) * KDIM + gch * 8;
    const __half* gAlo = Alo + (size_t)(bm * 128 + grow) * KDIM + gch * 8;
    const __half* gBhi = Bhi + (size_t)(bn * 128 + grow) * KDIM + gch * 8;
    const __half* gBlo = Blo + (size_t)(bn * 128 + grow) * KDIM + gch * 8;

    float acc[4][4][4];
    #pragma unroll
    for (int i = 0; i < 4; i++)
        #pragma unroll
        for (int j = 0; j < 4; j++)
            #pragma unroll
            for (int q = 0; q < 4; q++) acc[i][j][q] = 0.f;

    #pragma unroll
    for (int s = 0; s < NSTAGE - 1; s++) {
        uint32_t st = sbase + s * STAGE_BYTES;
        int k0 = s * 16;
        cp_async16(st + soff, gAhi + k0);
        if (TERMS >= 3) cp_async16(st + 4096 + soff, gAlo + k0);
        cp_async16(st + 8192 + soff, gBhi + k0);
        if (TERMS >= 2) cp_async16(st + 12288 + soff, gBlo + k0);
        cp_commit();
    }

    const int lrow = lane & 15, lhalf = lane >> 4;
    uint32_t offA[4], offB[2];
    #pragma unroll
    for (int mt = 0; mt < 4; mt++)
        offA[mt] = sw16(warpM * 64 + mt * 16 + lrow, lhalf);
    #pragma unroll
    for (int nt2 = 0; nt2 < 2; nt2++)
        offB[nt2] = sw16(warpN * 32 + nt2 * 16 + lrow, lhalf);

    for (int it = 0; it < KITER; it++) {
        cp_wait<NSTAGE - 2>();
        __syncthreads();

        if (it + NSTAGE - 1 < KITER) {
            int s = (it + NSTAGE - 1) % NSTAGE;
            uint32_t st = sbase + s * STAGE_BYTES;
            int k0 = (it + NSTAGE - 1) * 16;
            cp_async16(st + soff, gAhi + k0);
            if (TERMS >= 3) cp_async16(st + 4096 + soff, gAlo + k0);
            cp_async16(st + 8192 + soff, gBhi + k0);
            if (TERMS >= 2) cp_async16(st + 12288 + soff, gBlo + k0);
        }
        cp_commit();

        const uint32_t st = sbase + (it % NSTAGE) * STAGE_BYTES;

        uint32_t ah[4][4], al[4][4], bh[4][2], bl[4][2];
        #pragma unroll
        for (int mt = 0; mt < 4; mt++) {
            ldsm_x4(ah[mt][0], ah[mt][1], ah[mt][2], ah[mt][3], st + offA[mt]);
            if (TERMS >= 3)
                ldsm_x4(al[mt][0], al[mt][1], al[mt][2], al[mt][3],
                        st + 4096 + offA[mt]);
        }
        #pragma unroll
        for (int nt2 = 0; nt2 < 2; nt2++) {
            uint32_t r0, r1, r2, r3;
            ldsm_x4(r0, r1, r2, r3, st + 8192 + offB[nt2]);
            bh[nt2 * 2 + 0][0] = r0; bh[nt2 * 2 + 0][1] = r2;
            bh[nt2 * 2 + 1][0] = r1; bh[nt2 * 2 + 1][1] = r3;
            if (TERMS >= 2) {
                ldsm_x4(r0, r1, r2, r3, st + 12288 + offB[nt2]);
                bl[nt2 * 2 + 0][0] = r0; bl[nt2 * 2 + 0][1] = r2;
                bl[nt2 * 2 + 1][0] = r1; bl[nt2 * 2 + 1][1] = r3;
            }
        }
        #pragma unroll
        for (int mt = 0; mt < 4; mt++)
            #pragma unroll
            for (int nt = 0; nt < 4; nt++) {
                mma_f16(acc[mt][nt], ah[mt], bh[nt]);
                if (TERMS >= 2) mma_f16(acc[mt][nt], ah[mt], bl[nt]);
                if (TERMS >= 3) mma_f16(acc[mt][nt], al[mt], bh[nt]);
            }
    }

    cp_wait<0>();
    __syncthreads();   // before smem reuse as bounce

    if (MODE == 2) {
        #pragma unroll
        for (int mt = 0; mt < 4; mt++) {
            #pragma unroll
            for (int nt = 0; nt < 4; nt++) {
                int m0 = bm * 128 + warpM * 64 + mt * 16 + (lane >> 2);
                int n0 = bn * 128 + warpN * 32 + nt * 8 + (lane & 3) * 2;
                float2 bv = *(const float2*)(bias + n0);
                float2 v0 = make_float2(acc[mt][nt][0] + bv.x, acc[mt][nt][1] + bv.y);
                float2 v1 = make_float2(acc[mt][nt][2] + bv.x, acc[mt][nt][3] + bv.y);
                *(float2*)(C + (size_t)m0 * N + n0) = v0;
                *(float2*)(C + (size_t)(m0 + 8) * N + n0) = v1;
            }
        }
    } else {
        float* bounce = (float*)smem + wid * (32 * 65);
        #pragma unroll
        for (int mt = 0; mt < 4; mt++) {
            #pragma unroll
            for (int nt = 0; nt < 4; nt++) {
                int nl = nt * 8 + (lane & 3) * 2;
                int ml = mt * 16 + (lane >> 2);
                bounce[nl * 65 + ml]            = acc[mt][nt][0];
                bounce[(nl + 1) * 65 + ml]      = acc[mt][nt][1];
                bounce[nl * 65 + ml + 8]        = acc[mt][nt][2];
                bounce[(nl + 1) * 65 + ml + 8]  = acc[mt][nt][3];
            }
        }
        __syncwarp();
        int col = bn * 128 + warpN * 32 + lane;
        float bv = bias[col];
        const float* src = bounce + lane * 65;
        if (TERMS == 1) {
            __half* dst = g_vh + (size_t)(col - 1024) * MROWS
                        + bm * 128 + warpM * 64;
            #pragma unroll
            for (int q = 0; q < 16; q++) {
                __half h[4];
                h[0] = __float2half_rn(src[q * 4 + 0] + bv);
                h[1] = __float2half_rn(src[q * 4 + 1] + bv);
                h[2] = __float2half_rn(src[q * 4 + 2] + bv);
                h[3] = __float2half_rn(src[q * 4 + 3] + bv);
                *(uint2*)(dst + q * 4) = *(uint2*)h;
            }
        } else {
            float* dst = g_qkvT + (size_t)col * MROWS + bm * 128 + warpM * 64;
            #pragma unroll
            for (int q = 0; q < 16; q++) {
                float4 v;
                v.x = src[q * 4 + 0] + bv;
                v.y = src[q * 4 + 1] + bv;
                v.z = src[q * 4 + 2] + bv;
                v.w = src[q * 4 + 3] + bv;
                ((float4*)dst)[q] = v;
            }
        }
    }
}

// ---------------------------------------------------------------------------
// Attention: in-kernel Q/K hi-lo split -> HMMA 3-term scores -> IN-REGISTER
// softmax (quad shuffles + 1KB cross-warp stats exchange) -> fp16 P -> HMMA PV.
// sS eliminated entirely.
// ---------------------------------------------------------------------------
__global__ __launch_bounds__(256) void attn_kernel()
{
    __shared__ __align__(16) __half sQh[64 * 40];   // [l][d], 80B rows
    __shared__ __align__(16) __half sQl[64 * 40];
    __shared__ __align__(16) __half sKh[64 * 40];
    __shared__ __align__(16) __half sKl[64 * 40];
    __shared__ __align__(16) __half sVh[64 * 40];
    __shared__ __align__(16) __half sP[64 * 56];    // [l][m], 112B rows
    __shared__ float sXc[8][16][2];                  // per-warp row (max,sum)

    int tid = threadIdx.x;
    int b2 = blockIdx.x >> 4;
    int h  = blockIdx.x & 15;

    size_t base = (size_t)b2 * WINSTRIDE + (size_t)h * SLAB;
    const float*  Qg  = g_qkvT + base;
    const float*  Kg  = g_qkvT + PARTSTRIDE + base;
    const __half* Vgh = g_vh + base;
    const __half* bm  = g_bmh + ((size_t)(b2 & 63) * NHEAD + h) * LL;

    // V: 196 uint4 into 80B-stride rows
    if (tid < 196) {
        int row = tid >> 2, ch = tid & 3;
        *(uint4*)((char*)sVh + row * 80 + ch * 16) = ((const uint4*)Vgh)[tid];
    }
    // Q,K: load fp32, split hi/lo in registers, store fp16 planes
    for (int t = tid; t < SLAB / 4; t += 256) {
        float4 qv = ((const float4*)Qg)[t];
        float4 kv = ((const float4*)Kg)[t];
        int l = t >> 3;
        int doff = (t & 7) * 8;
        float qa[4] = {qv.x, qv.y, qv.z, qv.w};
        float ka[4] = {kv.x, kv.y, kv.z, kv.w};
        __half qh[4], ql[4], kh[4], kl[4];
        #pragma unroll
        for (int j = 0; j < 4; j++) {
            qh[j] = __float2half_rn(qa[j]);
            ql[j] = __float2half_rn(qa[j] - __half2float(qh[j]));
            kh[j] = __float2half_rn(ka[j]);
            kl[j] = __float2half_rn(ka[j] - __half2float(kh[j]));
        }
        uint32_t d = (uint32_t)l * 80u + (uint32_t)doff;
        *(uint2*)((char*)sQh + d) = *(uint2*)qh;
        *(uint2*)((char*)sQl + d) = *(uint2*)ql;
        *(uint2*)((char*)sKh + d) = *(uint2*)kh;
        *(uint2*)((char*)sKl + d) = *(uint2*)kl;
    }
    __syncthreads();

    // Scores + fused softmax. Warp w: m-tile (w>>1, 16 rows), n-half (w&1).
    {
        int w = tid >> 5, lane = tid & 31;
        int mt = w >> 1, nh = w & 1;
        uint32_t uQh = smem_u32(sQh), uQl = smem_u32(sQl);
        uint32_t uKh = smem_u32(sKh), uKl = smem_u32(sKl);
        uint32_t aoff  = (uint32_t)(mt * 16 + (lane & 15)) * 80u
                       + (uint32_t)(lane >> 4) * 16u;
        uint32_t boff0 = (uint32_t)(nh * 32 + (lane & 15)) * 80u
                       + (uint32_t)(lane >> 4) * 16u;
        uint32_t boff1 = boff0 + 16u * 80u;

        float acc[4][4];
        #pragma unroll
        for (int i = 0; i < 4; i++)
            #pragma unroll
            for (int j = 0; j < 4; j++) acc[i][j] = 0.f;

        #pragma unroll
        for (int ks = 0; ks < 2; ks++) {
            uint32_t kb = ks * 32u;
            uint32_t qh[4], ql[4], kh[4][2], kl[4][2];
            ldsm_x4(qh[0], qh[1], qh[2], qh[3], uQh + aoff + kb);
            ldsm_x4(ql[0], ql[1], ql[2], ql[3], uQl + aoff + kb);
            uint32_t r0, r1, r2, r3;
            ldsm_x4(r0, r1, r2, r3, uKh + boff0 + kb);
            kh[0][0] = r0; kh[0][1] = r2; kh[1][0] = r1; kh[1][1] = r3;
            ldsm_x4(r0, r1, r2, r3, uKh + boff1 + kb);
            kh[2][0] = r0; kh[2][1] = r2; kh[3][0] = r1; kh[3][1] = r3;
            ldsm_x4(r0, r1, r2, r3, uKl + boff0 + kb);
            kl[0][0] = r0; kl[0][1] = r2; kl[1][0] = r1; kl[1][1] = r3;
            ldsm_x4(r0, r1, r2, r3, uKl + boff1 + kb);
            kl[2][0] = r0; kl[2][1] = r2; kl[3][0] = r1; kl[3][1] = r3;
            #pragma unroll
            for (int nt = 0; nt < 4; nt++) {
                mma_f16(acc[nt], qh, kh[nt]);
                mma_f16(acc[nt], qh, kl[nt]);
                mma_f16(acc[nt], ql, kh[nt]);
            }
        }

        // add bias+mask in-register; cols >= 49 -> -inf
        int rA = mt * 16 + (lane >> 2);       // hf=0 row
        #pragma unroll
        for (int nt = 0; nt < 4; nt++) {
            int c0 = nh * 32 + nt * 8 + (lane & 3) * 2;
            #pragma unroll
            for (int hf = 0; hf < 2; hf++) {
                int r = rA + hf * 8;
                #pragma unroll
                for (int j = 0; j < 2; j++) {
                    int c = c0 + j;
                    float& v = acc[nt][hf * 2 + j];
                    if (c >= LTOK) v = -CUDART_INF_F;
                    else if (r < LTOK)
                        v += __half2float(bm[r * LTOK + c]);
                }
            }
        }

        // in-register softmax stats per row (2 rows per thread)
        float mrow[2], srow[2];
        #pragma unroll
        for (int hf = 0; hf < 2; hf++) {
            float m = -CUDART_INF_F;
            #pragma unroll
            for (int nt = 0; nt < 4; nt++) {
                m = fmaxf(m, acc[nt][hf * 2 + 0]);
                m = fmaxf(m, acc[nt][hf * 2 + 1]);
            }
            m = fmaxf(m, __shfl_xor_sync(0xffffffffu, m, 1));
            m = fmaxf(m, __shfl_xor_sync(0xffffffffu, m, 2));
            float s = 0.f;
            #pragma unroll
            for (int nt = 0; nt < 4; nt++) {
                #pragma unroll
                for (int j = 0; j < 2; j++) {
                    float e = __expf(acc[nt][hf * 2 + j] - m);
                    acc[nt][hf * 2 + j] = e;    // overwrite with exp(v - m)
                    s += e;
                }
            }
            s += __shfl_xor_sync(0xffffffffu, s, 1);
            s += __shfl_xor_sync(0xffffffffu, s, 2);
            mrow[hf] = m;
            srow[hf] = s;
        }
        if ((lane & 3) == 0) {
            int rloc = lane >> 2;
            sXc[w][rloc][0] = mrow[0];
            sXc[w][rloc][1] = srow[0];
            sXc[w][rloc + 8][0] = mrow[1];
            sXc[w][rloc + 8][1] = srow[1];
        }
        __syncthreads();

        // combine with sibling warp (other n-half), write P fp16
        #pragma unroll
        for (int hf = 0; hf < 2; hf++) {
            int rloc = (lane >> 2) + hf * 8;
            float m2 = sXc[w ^ 1][rloc][0];
            float s2 = sXc[w ^ 1][rloc][1];
            float M = fmaxf(mrow[hf], m2);
            float S = srow[hf] * __expf(mrow[hf] - M)
                    + s2 * __expf(m2 - M);
            float scale = __expf(mrow[hf] - M) / S;
            int r = rA + hf * 8;
            #pragma unroll
            for (int nt = 0; nt < 4; nt++) {
                int c = nh * 32 + nt * 8 + (lane & 3) * 2;
                if (c < LTOK) {
                    __half2 p = __floats2half2_rn(
                        acc[nt][hf * 2 + 0] * scale,
                        acc[nt][hf * 2 + 1] * scale);
                    *(__half2*)&sP[r * 56 + c] = p;
                }
            }
        }
    }
    __syncthreads();

    // PV via HMMA: O[64l x 32d] = P[64 x 49] * V[49 x 32]  (verified R12/R13)
    {
        int w = tid >> 5, lane = tid & 31;
        int mt = w >> 1, dh = w & 1;
        uint32_t uP = smem_u32(sP), uV = smem_u32(sVh);
        uint32_t aoff = (uint32_t)(mt * 16 + (lane & 15)) * 112u
                      + (uint32_t)(lane >> 4) * 16u;
        uint32_t boff = (uint32_t)(lane & 15) * 80u
                      + (uint32_t)(lane >> 4) * 16u + (uint32_t)dh * 32u;

        float acc[2][4];
        #pragma unroll
        for (int nt = 0; nt < 2; nt++)
            #pragma unroll
            for (int q = 0; q < 4; q++) acc[nt][q] = 0.f;

        #pragma unroll
        for (int kc = 0; kc < 3; kc++) {
            uint32_t a[4];
            ldsm_x4(a[0], a[1], a[2], a[3], uP + aoff + kc * 32u);
            uint32_t r0, r1, r2, r3;
            ldsm_x4_trans(r0, r1, r2, r3, uV + boff + kc * (16u * 80u));
            uint32_t b0[2] = {r0, r1};
            uint32_t b1[2] = {r2, r3};
            mma_f16(acc[0], a, b0);
            mma_f16(acc[1], a, b1);
        }

        // fixup m=48
        int l0 = mt * 16 + (lane >> 2);
        float pA = __half2float(sP[l0 * 56 + 48]);
        float pB = __half2float(sP[(l0 + 8) * 56 + 48]);
        #pragma unroll
        for (int nt = 0; nt < 2; nt++) {
            int d = dh * 16 + nt * 8 + (lane & 3) * 2;
            float v0 = __half2float(sVh[48 * 40 + d]);
            float v1 = __half2float(sVh[48 * 40 + d + 1]);
            acc[nt][0] += pA * v0;
            acc[nt][1] += pA * v1;
            acc[nt][2] += pB * v0;
            acc[nt][3] += pB * v1;
        }

        // store (guard l < 49)
        #pragma unroll
        for (int nt = 0; nt < 2; nt++) {
            int d = dh * 16 + nt * 8 + (lane & 3) * 2;
            #pragma unroll
            for (int hf = 0; hf < 2; hf++) {
                int l = mt * 16 + (lane >> 2) + hf * 8;
                if (l < LTOK) {
                    size_t oidx = ((size_t)b2 * LTOK + l) * CDIM + h * HD + d;
                    *(__half2*)(g_ohi + oidx) =
                        __floats2half2_rn(acc[nt][hf * 2], acc[nt][hf * 2 + 1]);
                }
            }
        }
    }
}

// ---------------------------------------------------------------------------
extern "C" void kernel_launch(void* const* d_in, const int* in_sizes, int n_in,
                              void* d_out, int out_size)
{
    const float* x           = (const float*)d_in[0];
    const float* mask        = (const float*)d_in[1];
    const float* w_qkv       = (const float*)d_in[2];
    const float* b_qkv       = (const float*)d_in[3];
    const float* w_proj      = (const float*)d_in[4];
    const float* b_proj      = (const float*)d_in[5];
    const float* bias_table  = (const float*)d_in[6];
    const int*   index_table = (const int*)d_in[7];
    float* out = (float*)d_out;

    cudaFuncSetAttribute(gemm_f16x3<1, 3>, cudaFuncAttributeMaxDynamicSharedMemorySize, DYN_SMEM);
    cudaFuncSetAttribute(gemm_f16x3<1, 1>, cudaFuncAttributeMaxDynamicSharedMemorySize, DYN_SMEM);
    cudaFuncSetAttribute(gemm_f16x3<2, 1>, cudaFuncAttributeMaxDynamicSharedMemorySize, DYN_SMEM);

    // 0) weight transpose+split, x split, fused bias+mask table (fp16)
    wtrans_kernel<1><<<dim3(NQKV / 32, KDIM / 32), dim3(32, 8)>>>(w_qkv, KDIM, NQKV);
    wtrans_kernel<2><<<dim3(CDIM / 32, KDIM / 32), dim3(32, 8)>>>(w_proj, KDIM, CDIM);
    split_x_kernel<<<((size_t)MROWS * CDIM) / 4 / 256, 256>>>(x);
    biasmask_kernel<<<64 * NHEAD, 256>>>(mask, bias_table, index_table);

    // 1a) QK columns (0..1023): 3-term fp32 scatter (16B granules)
    gemm_f16x3<1, 3><<<dim3(8, MROWS / 128), 256, DYN_SMEM>>>(b_qkv, nullptr, NQKV, 0);
    // 1b) V columns (1024..1535): 1-term fp16 scatter
    gemm_f16x3<1, 1><<<dim3(4, MROWS / 128), 256, DYN_SMEM>>>(b_qkv, nullptr, NQKV, 8);

    // 2) fused window attention (HMMA scores + in-register softmax + HMMA PV)
    attn_kernel<<<BNW * NHEAD, 256>>>();

    // 3) projection GEMM: 1-term
    gemm_f16x3<2, 1><<<dim3(4, MROWS / 128), 256, DYN_SMEM>>>(b_proj, out, CDIM, 0);
}

// round 16
// speedup vs baseline: 1.2189x; 1.0081x over previous
#include <cuda_runtime.h>
#include <cuda_fp16.h>
#include <cstdint>
#include <math_constants.h>

// Problem constants
#define CDIM 512
#define NHEAD 16
#define HD 32
#define LTOK 49
#define BNW 4096
#define MROWS (BNW * LTOK)            // 200704
#define NQKV (3 * CDIM)               // 1536
#define SLAB (LTOK * HD)              // 1568
#define WINSTRIDE (NHEAD * SLAB)      // 25088
#define PARTSTRIDE ((size_t)CDIM * MROWS)
#define KDIM 512
#define KITER (KDIM / 16)             // 32 iters of K=16
#define LL (LTOK * LTOK)               // 2401
#define HALF_BM 784                    // G2 row blocks per chain
#define HALF_WIN 2048

// Scratch (device globals — no allocation)
__device__ float  g_qkvT[(size_t)1024 * MROWS];     // Q,K channel-major fp32
__device__ __half g_vh[(size_t)CDIM * MROWS];       // V channel-major fp16
__device__ __half g_xhi[(size_t)MROWS * CDIM];      // x split hi/lo
__device__ __half g_xlo[(size_t)MROWS * CDIM];
__device__ __half g_ohi[(size_t)MROWS * CDIM];      // attn out, fp16 (hi only)
__device__ __half g_whi1[(size_t)NQKV * KDIM];      // w_qkv^T hi/lo [N][K]
__device__ __half g_wlo1[(size_t)NQKV * KDIM];
__device__ __half g_whi2[(size_t)CDIM * KDIM];      // w_proj^T hi (1-term)
__device__ __half g_wlo2[(size_t)CDIM * KDIM];
__device__ __half g_bmh[64 * NHEAD * LL];           // fused bias+mask, fp16

// ---------------------------------------------------------------------------
// PTX helpers (sm_80-era ISA — tcgen05 unavailable at compute_103)
// ---------------------------------------------------------------------------
__device__ __forceinline__ uint32_t smem_u32(const void* p) {
    uint32_t a;
    asm("{ .reg .u64 t; cvta.to.shared.u64 t, %1; cvt.u32.u64 %0, t; }"
        : "=r"(a) : "l"(p));
    return a;
}
__device__ __forceinline__ void cp_async16(uint32_t smem, const void* g) {
    asm volatile("cp.async.cg.shared.global [%0], [%1], 16;"
                 :: "r"(smem), "l"(g) : "memory");
}
__device__ __forceinline__ void cp_commit() {
    asm volatile("cp.async.commit_group;" ::: "memory");
}
template <int N>
__device__ __forceinline__ void cp_wait() {
    asm volatile("cp.async.wait_group %0;" :: "n"(N) : "memory");
}
__device__ __forceinline__ void ldsm_x4(uint32_t& r0, uint32_t& r1,
                                        uint32_t& r2, uint32_t& r3,
                                        uint32_t addr) {
    asm volatile("ldmatrix.sync.aligned.m8n8.x4.shared.b16 {%0,%1,%2,%3}, [%4];"
                 : "=r"(r0), "=r"(r1), "=r"(r2), "=r"(r3) : "r"(addr));
}
__device__ __forceinline__ void ldsm_x4_trans(uint32_t& r0, uint32_t& r1,
                                              uint32_t& r2, uint32_t& r3,
                                              uint32_t addr) {
    asm volatile("ldmatrix.sync.aligned.m8n8.x4.trans.shared.b16 {%0,%1,%2,%3}, [%4];"
                 : "=r"(r0), "=r"(r1), "=r"(r2), "=r"(r3) : "r"(addr));
}
__device__ __forceinline__ void mma_f16(float* d, const uint32_t* a,
                                        const uint32_t* b) {
    asm volatile(
        "mma.sync.aligned.m16n8k16.row.col.f32.f16.f16.f32 "
        "{%0,%1,%2,%3}, {%4,%5,%6,%7}, {%8,%9}, {%0,%1,%2,%3};"
        : "+f"(d[0]), "+f"(d[1]), "+f"(d[2]), "+f"(d[3])
        : "r"(a[0]), "r"(a[1]), "r"(a[2]), "r"(a[3]), "r"(b[0]), "r"(b[1]));
}

#define STAGE_BYTES 16384
#define NSTAGE 4
#define DYN_SMEM 66560   // max(4*16384, 8 warps * 32*65*4 bounce)

__device__ __forceinline__ uint32_t sw16(int row, int c) {
    return (uint32_t)row * 32u + (uint32_t)((c ^ ((row >> 2) & 1)) << 4);
}

// ---------------------------------------------------------------------------
// x -> hi/lo fp16 split (elementwise)
// ---------------------------------------------------------------------------
__global__ __launch_bounds__(256) void split_x_kernel(const float* __restrict__ src) {
    size_t i = ((size_t)blockIdx.x * 256 + threadIdx.x) * 4;
    float4 v = *(const float4*)(src + i);
    __half h0 = __float2half_rn(v.x), h1 = __float2half_rn(v.y);
    __half h2 = __float2half_rn(v.z), h3 = __float2half_rn(v.w);
    __half l0 = __float2half_rn(v.x - __half2float(h0));
    __half l1 = __float2half_rn(v.y - __half2float(h1));
    __half l2 = __float2half_rn(v.z - __half2float(h2));
    __half l3 = __float2half_rn(v.w - __half2float(h3));
    __half2 hh[2] = {__halves2half2(h0, h1), __halves2half2(h2, h3)};
    __half2 ll[2] = {__halves2half2(l0, l1), __halves2half2(l2, l3)};
    *(uint2*)(g_xhi + i) = *(uint2*)hh;
    *(uint2*)(g_xlo + i) = *(uint2*)ll;
}

// ---------------------------------------------------------------------------
// Weight transpose + split: src[k*N + n] -> dst_{hi,lo}[n*K + k]
// ---------------------------------------------------------------------------
template <int SEL>
__global__ void wtrans_kernel(const float* __restrict__ src, int K, int N) {
    __half* dhi = (SEL == 1) ? g_whi1 : g_whi2;
    __half* dlo = (SEL == 1) ? g_wlo1 : g_wlo2;
    __shared__ float t[32][33];
    int n0 = blockIdx.x * 32, k0 = blockIdx.y * 32;
    int x = threadIdx.x, y = threadIdx.y;
    #pragma unroll
    for (int i = y; i < 32; i += 8)
        t[i][x] = src[(size_t)(k0 + i) * N + n0 + x];
    __syncthreads();
    #pragma unroll
    for (int i = y; i < 32; i += 8) {
        float v = t[x][i];
        __half h = __float2half_rn(v);
        __half l = __float2half_rn(v - __half2float(h));
        dhi[(size_t)(n0 + i) * K + k0 + x] = h;
        dlo[(size_t)(n0 + i) * K + k0 + x] = l;
    }
}

// ---------------------------------------------------------------------------
// Fused bias+mask precompute (fp16 output)
// ---------------------------------------------------------------------------
__global__ __launch_bounds__(256) void biasmask_kernel(
    const float* __restrict__ mask,
    const float* __restrict__ bias_table,
    const int*   __restrict__ index_table)
{
    int wh = blockIdx.x;
    int w = wh >> 4, h = wh & 15;
    const float* mrow = mask + (size_t)w * LL;
    __half* dst = g_bmh + (size_t)wh * LL;
    for (int o = threadIdx.x; o < LL; o += 256)
        dst[o] = __float2half_rn(bias_table[index_table[o] * NHEAD + h] + mrow[o]);
}

// ---------------------------------------------------------------------------
// fp16 split GEMM (256 thr, 2x4 warps, 64x32 warp tile).
// MODE1/TERMS3: QK col-blocks bn = bnOff + (bx&1) + (bx>>1)*4, all rows
// MODE1/TERMS1: V col-blocks  bn = bnOff + bx, all rows
// MODE2/TERMS1: proj, bn = bx (all cols), bm = by + bmOff (row half)
// ---------------------------------------------------------------------------
template <int MODE, int TERMS>
__global__ __launch_bounds__(256) void gemm_f16x3(
    const float* __restrict__ bias, float* __restrict__ C, int N, int bnOff,
    int bmOff)
{
    extern __shared__ char smem[];
    const __half* Ahi = (MODE == 1) ? g_xhi : g_ohi;
    const __half* Alo = (MODE == 1) ? g_xlo : g_ohi;   // dummy when TERMS<3
    const __half* Bhi = (MODE == 1) ? g_whi1 : g_whi2;
    const __half* Blo = (MODE == 1) ? g_wlo1 : g_wlo2;

    const int tid = threadIdx.x;
    const int lane = tid & 31, wid = tid >> 5;
    const int warpM = wid & 1, warpN = wid >> 1;   // 2 x 4 warps, 64x32 tiles
    int bn;
    if (MODE == 1 && TERMS == 3)
        bn = bnOff + (blockIdx.x & 1) + ((blockIdx.x >> 1) << 2);
    else if (MODE == 1)
        bn = bnOff + blockIdx.x;
    else
        bn = blockIdx.x;
    const int bm = blockIdx.y + bmOff;
    const uint32_t sbase = smem_u32(smem);

    const int grow = tid >> 1, gch = tid & 1;
    const uint32_t soff = sw16(grow, gch);
    const __half* gAhi = Ahi + (size_t)(bm * 128 + grow) * KDIM + gch * 8;
    const __half* gAlo = Alo + (size_t)(bm * 128 + grow) * KDIM + gch * 8;
    const __half* gBhi = Bhi + (size_t)(bn * 128 + grow) * KDIM + gch * 8;
    const __half* gBlo = Blo + (size_t)(bn * 128 + grow) * KDIM + gch * 8;

    float acc[4][4][4];
    #pragma unroll
    for (int i = 0; i < 4; i++)
        #pragma unroll
        for (int j = 0; j < 4; j++)
            #pragma unroll
            for (int q = 0; q < 4; q++) acc[i][j][q] = 0.f;

    #pragma unroll
    for (int s = 0; s < NSTAGE - 1; s++) {
        uint32_t st = sbase + s * STAGE_BYTES;
        int k0 = s * 16;
        cp_async16(st + soff, gAhi + k0);
        if (TERMS >= 3) cp_async16(st + 4096 + soff, gAlo + k0);
        cp_async16(st + 8192 + soff, gBhi + k0);
        if (TERMS >= 2) cp_async16(st + 12288 + soff, gBlo + k0);
        cp_commit();
    }

    const int lrow = lane & 15, lhalf = lane >> 4;
    uint32_t offA[4], offB[2];
    #pragma unroll
    for (int mt = 0; mt < 4; mt++)
        offA[mt] = sw16(warpM * 64 + mt * 16 + lrow, lhalf);
    #pragma unroll
    for (int nt2 = 0; nt2 < 2; nt2++)
        offB[nt2] = sw16(warpN * 32 + nt2 * 16 + lrow, lhalf);

    for (int it = 0; it < KITER; it++) {
        cp_wait<NSTAGE - 2>();
        __syncthreads();

        if (it + NSTAGE - 1 < KITER) {
            int s = (it + NSTAGE - 1) % NSTAGE;
            uint32_t st = sbase + s * STAGE_BYTES;
            int k0 = (it + NSTAGE - 1) * 16;
            cp_async16(st + soff, gAhi + k0);
            if (TERMS >= 3) cp_async16(st + 4096 + soff, gAlo + k0);
            cp_async16(st + 8192 + soff, gBhi + k0);
            if (TERMS >= 2) cp_async16(st + 12288 + soff, gBlo + k0);
        }
        cp_commit();

        const uint32_t st = sbase + (it % NSTAGE) * STAGE_BYTES;

        uint32_t ah[4][4], al[4][4], bh[4][2], bl[4][2];
        #pragma unroll
        for (int mt = 0; mt < 4; mt++) {
            ldsm_x4(ah[mt][0], ah[mt][1], ah[mt][2], ah[mt][3], st + offA[mt]);
            if (TERMS >= 3)
                ldsm_x4(al[mt][0], al[mt][1], al[mt][2], al[mt][3],
                        st + 4096 + offA[mt]);
        }
        #pragma unroll
        for (int nt2 = 0; nt2 < 2; nt2++) {
            uint32_t r0, r1, r2, r3;
            ldsm_x4(r0, r1, r2, r3, st + 8192 + offB[nt2]);
            bh[nt2 * 2 + 0][0] = r0; bh[nt2 * 2 + 0][1] = r2;
            bh[nt2 * 2 + 1][0] = r1; bh[nt2 * 2 + 1][1] = r3;
            if (TERMS >= 2) {
                ldsm_x4(r0, r1, r2, r3, st + 12288 + offB[nt2]);
                bl[nt2 * 2 + 0][0] = r0; bl[nt2 * 2 + 0][1] = r2;
                bl[nt2 * 2 + 1][0] = r1; bl[nt2 * 2 + 1][1] = r3;
            }
        }
        #pragma unroll
        for (int mt = 0; mt < 4; mt++)
            #pragma unroll
            for (int nt = 0; nt < 4; nt++) {
                mma_f16(acc[mt][nt], ah[mt], bh[nt]);
                if (TERMS >= 2) mma_f16(acc[mt][nt], ah[mt], bl[nt]);
                if (TERMS >= 3) mma_f16(acc[mt][nt], al[mt], bh[nt]);
            }
    }

    cp_wait<0>();
    __syncthreads();   // before smem reuse as bounce

    if (MODE == 2) {
        #pragma unroll
        for (int mt = 0; mt < 4; mt++) {
            #pragma unroll
            for (int nt = 0; nt < 4; nt++) {
                int m0 = bm * 128 + warpM * 64 + mt * 16 + (lane >> 2);
                int n0 = bn * 128 + warpN * 32 + nt * 8 + (lane & 3) * 2;
                float2 bv = *(const float2*)(bias + n0);
                float2 v0 = make_float2(acc[mt][nt][0] + bv.x, acc[mt][nt][1] + bv.y);
                float2 v1 = make_float2(acc[mt][nt][2] + bv.x, acc[mt][nt][3] + bv.y);
                *(float2*)(C + (size_t)m0 * N + n0) = v0;
                *(float2*)(C + (size_t)(m0 + 8) * N + n0) = v1;
            }
        }
    } else {
        float* bounce = (float*)smem + wid * (32 * 65);
        #pragma unroll
        for (int mt = 0; mt < 4; mt++) {
            #pragma unroll
            for (int nt = 0; nt < 4; nt++) {
                int nl = nt * 8 + (lane & 3) * 2;
                int ml = mt * 16 + (lane >> 2);
                bounce[nl * 65 + ml]            = acc[mt][nt][0];
                bounce[(nl + 1) * 65 + ml]      = acc[mt][nt][1];
                bounce[nl * 65 + ml + 8]        = acc[mt][nt][2];
                bounce[(nl + 1) * 65 + ml + 8]  = acc[mt][nt][3];
            }
        }
        __syncwarp();
        int col = bn * 128 + warpN * 32 + lane;
        float bv = bias[col];
        const float* src = bounce + lane * 65;
        if (TERMS == 1) {
            __half* dst = g_vh + (size_t)(col - 1024) * MROWS
                        + bm * 128 + warpM * 64;
            #pragma unroll
            for (int q = 0; q < 16; q++) {
                __half h[4];
                h[0] = __float2half_rn(src[q * 4 + 0] + bv);
                h[1] = __float2half_rn(src[q * 4 + 1] + bv);
                h[2] = __float2half_rn(src[q * 4 + 2] + bv);
                h[3] = __float2half_rn(src[q * 4 + 3] + bv);
                *(uint2*)(dst + q * 4) = *(uint2*)h;
            }
        } else {
            float* dst = g_qkvT + (size_t)col * MROWS + bm * 128 + warpM * 64;
            #pragma unroll
            for (int q = 0; q < 16; q++) {
                float4 v;
                v.x = src[q * 4 + 0] + bv;
                v.y = src[q * 4 + 1] + bv;
                v.z = src[q * 4 + 2] + bv;
                v.w = src[q * 4 + 3] + bv;
                ((float4*)dst)[q] = v;
            }
        }
    }
}

// ---------------------------------------------------------------------------
// Attention (identical math to R14): b2Off = window offset for the chain.
// ---------------------------------------------------------------------------
__global__ __launch_bounds__(256) void attn_kernel(int b2Off)
{
    __shared__ __align__(16) __half sQh[64 * 40];
    __shared__ __align__(16) __half sQl[64 * 40];
    __shared__ __align__(16) __half sKh[64 * 40];
    __shared__ __align__(16) __half sKl[64 * 40];
    __shared__ __align__(16) __half sVh[64 * 40];
    __shared__ __align__(16) __half sP[64 * 56];
    __shared__ float sXc[8][16][2];

    int tid = threadIdx.x;
    int b2 = b2Off + (blockIdx.x >> 4);
    int h  = blockIdx.x & 15;

    size_t base = (size_t)b2 * WINSTRIDE + (size_t)h * SLAB;
    const float*  Qg  = g_qkvT + base;
    const float*  Kg  = g_qkvT + PARTSTRIDE + base;
    const __half* Vgh = g_vh + base;
    const __half* bm  = g_bmh + ((size_t)(b2 & 63) * NHEAD + h) * LL;

    if (tid < 196) {
        int row = tid >> 2, ch = tid & 3;
        *(uint4*)((char*)sVh + row * 80 + ch * 16) = ((const uint4*)Vgh)[tid];
    }
    for (int t = tid; t < SLAB / 4; t += 256) {
        float4 qv = ((const float4*)Qg)[t];
        float4 kv = ((const float4*)Kg)[t];
        int l = t >> 3;
        int doff = (t & 7) * 8;
        float qa[4] = {qv.x, qv.y, qv.z, qv.w};
        float ka[4] = {kv.x, kv.y, kv.z, kv.w};
        __half qh[4], ql[4], kh[4], kl[4];
        #pragma unroll
        for (int j = 0; j < 4; j++) {
            qh[j] = __float2half_rn(qa[j]);
            ql[j] = __float2half_rn(qa[j] - __half2float(qh[j]));
            kh[j] = __float2half_rn(ka[j]);
            kl[j] = __float2half_rn(ka[j] - __half2float(kh[j]));
        }
        uint32_t d = (uint32_t)l * 80u + (uint32_t)doff;
        *(uint2*)((char*)sQh + d) = *(uint2*)qh;
        *(uint2*)((char*)sQl + d) = *(uint2*)ql;
        *(uint2*)((char*)sKh + d) = *(uint2*)kh;
        *(uint2*)((char*)sKl + d) = *(uint2*)kl;
    }
    __syncthreads();

    {
        int w = tid >> 5, lane = tid & 31;
        int mt = w >> 1, nh = w & 1;
        uint32_t uQh = smem_u32(sQh), uQl = smem_u32(sQl);
        uint32_t uKh = smem_u32(sKh), uKl = smem_u32(sKl);
        uint32_t aoff  = (uint32_t)(mt * 16 + (lane & 15)) * 80u
                       + (uint32_t)(lane >> 4) * 16u;
        uint32_t boff0 = (uint32_t)(nh * 32 + (lane & 15)) * 80u
                       + (uint32_t)(lane >> 4) * 16u;
        uint32_t boff1 = boff0 + 16u * 80u;

        float acc[4][4];
        #pragma unroll
        for (int i = 0; i < 4; i++)
            #pragma unroll
            for (int j = 0; j < 4; j++) acc[i][j] = 0.f;

        #pragma unroll
        for (int ks = 0; ks < 2; ks++) {
            uint32_t kb = ks * 32u;
            uint32_t qh[4], ql[4], kh[4][2], kl[4][2];
            ldsm_x4(qh[0], qh[1], qh[2], qh[3], uQh + aoff + kb);
            ldsm_x4(ql[0], ql[1], ql[2], ql[3], uQl + aoff + kb);
            uint32_t r0, r1, r2, r3;
            ldsm_x4(r0, r1, r2, r3, uKh + boff0 + kb);
            kh[0][0] = r0; kh[0][1] = r2; kh[1][0] = r1; kh[1][1] = r3;
            ldsm_x4(r0, r1, r2, r3, uKh + boff1 + kb);
            kh[2][0] = r0; kh[2][1] = r2; kh[3][0] = r1; kh[3][1] = r3;
            ldsm_x4(r0, r1, r2, r3, uKl + boff0 + kb);
            kl[0][0] = r0; kl[0][1] = r2; kl[1][0] = r1; kl[1][1] = r3;
            ldsm_x4(r0, r1, r2, r3, uKl + boff1 + kb);
            kl[2][0] = r0; kl[2][1] = r2; kl[3][0] = r1; kl[3][1] = r3;
            #pragma unroll
            for (int nt = 0; nt < 4; nt++) {
                mma_f16(acc[nt], qh, kh[nt]);
                mma_f16(acc[nt], qh, kl[nt]);
                mma_f16(acc[nt], ql, kh[nt]);
            }
        }

        int rA = mt * 16 + (lane >> 2);
        #pragma unroll
        for (int nt = 0; nt < 4; nt++) {
            int c0 = nh * 32 + nt * 8 + (lane & 3) * 2;
            #pragma unroll
            for (int hf = 0; hf < 2; hf++) {
                int r = rA + hf * 8;
                #pragma unroll
                for (int j = 0; j < 2; j++) {
                    int c = c0 + j;
                    float& v = acc[nt][hf * 2 + j];
                    if (c >= LTOK) v = -CUDART_INF_F;
                    else if (r < LTOK)
                        v += __half2float(bm[r * LTOK + c]);
                }
            }
        }

        float mrow[2], srow[2];
        #pragma unroll
        for (int hf = 0; hf < 2; hf++) {
            float m = -CUDART_INF_F;
            #pragma unroll
            for (int nt = 0; nt < 4; nt++) {
                m = fmaxf(m, acc[nt][hf * 2 + 0]);
                m = fmaxf(m, acc[nt][hf * 2 + 1]);
            }
            m = fmaxf(m, __shfl_xor_sync(0xffffffffu, m, 1));
            m = fmaxf(m, __shfl_xor_sync(0xffffffffu, m, 2));
            float s = 0.f;
            #pragma unroll
            for (int nt = 0; nt < 4; nt++) {
                #pragma unroll
                for (int j = 0; j < 2; j++) {
                    float e = __expf(acc[nt][hf * 2 + j] - m);
                    acc[nt][hf * 2 + j] = e;
                    s += e;
                }
            }
            s += __shfl_xor_sync(0xffffffffu, s, 1);
            s += __shfl_xor_sync(0xffffffffu, s, 2);
            mrow[hf] = m;
            srow[hf] = s;
        }
        if ((lane & 3) == 0) {
            int rloc = lane >> 2;
            sXc[w][rloc][0] = mrow[0];
            sXc[w][rloc][1] = srow[0];
            sXc[w][rloc + 8][0] = mrow[1];
            sXc[w][rloc + 8][1] = srow[1];
        }
        __syncthreads();

        #pragma unroll
        for (int hf = 0; hf < 2; hf++) {
            int rloc = (lane >> 2) + hf * 8;
            float m2 = sXc[w ^ 1][rloc][0];
            float s2 = sXc[w ^ 1][rloc][1];
            float M = fmaxf(mrow[hf], m2);
            float S = srow[hf] * __expf(mrow[hf] - M)
                    + s2 * __expf(m2 - M);
            float scale = __expf(mrow[hf] - M) / S;
            int r = rA + hf * 8;
            #pragma unroll
            for (int nt = 0; nt < 4; nt++) {
                int c = nh * 32 + nt * 8 + (lane & 3) * 2;
                if (c < LTOK) {
                    __half2 p = __floats2half2_rn(
                        acc[nt][hf * 2 + 0] * scale,
                        acc[nt][hf * 2 + 1] * scale);
                    *(__half2*)&sP[r * 56 + c] = p;
                }
            }
        }
    }
    __syncthreads();

    {
        int w = tid >> 5, lane = tid & 31;
        int mt = w >> 1, dh = w & 1;
        uint32_t uP = smem_u32(sP), uV = smem_u32(sVh);
        uint32_t aoff = (uint32_t)(mt * 16 + (lane & 15)) * 112u
                      + (uint32_t)(lane >> 4) * 16u;
        uint32_t boff = (uint32_t)(lane & 15) * 80u
                      + (uint32_t)(lane >> 4) * 16u + (uint32_t)dh * 32u;

        float acc[2][4];
        #pragma unroll
        for (int nt = 0; nt < 2; nt++)
            #pragma unroll
            for (int q = 0; q < 4; q++) acc[nt][q] = 0.f;

        #pragma unroll
        for (int kc = 0; kc < 3; kc++) {
            uint32_t a[4];
            ldsm_x4(a[0], a[1], a[2], a[3], uP + aoff + kc * 32u);
            uint32_t r0, r1, r2, r3;
            ldsm_x4_trans(r0, r1, r2, r3, uV + boff + kc * (16u * 80u));
            uint32_t b0[2] = {r0, r1};
            uint32_t b1[2] = {r2, r3};
            mma_f16(acc[0], a, b0);
            mma_f16(acc[1], a, b1);
        }

        int l0 = mt * 16 + (lane >> 2);
        float pA = __half2float(sP[l0 * 56 + 48]);
        float pB = __half2float(sP[(l0 + 8) * 56 + 48]);
        #pragma unroll
        for (int nt = 0; nt < 2; nt++) {
            int d = dh * 16 + nt * 8 + (lane & 3) * 2;
            float v0 = __half2float(sVh[48 * 40 + d]);
            float v1 = __half2float(sVh[48 * 40 + d + 1]);
            acc[nt][0] += pA * v0;
            acc[nt][1] += pA * v1;
            acc[nt][2] += pB * v0;
            acc[nt][3] += pB * v1;
        }

        #pragma unroll
        for (int nt = 0; nt < 2; nt++) {
            int d = dh * 16 + nt * 8 + (lane & 3) * 2;
            #pragma unroll
            for (int hf = 0; hf < 2; hf++) {
                int l = mt * 16 + (lane >> 2) + hf * 8;
                if (l < LTOK) {
                    size_t oidx = ((size_t)b2 * LTOK + l) * CDIM + h * HD + d;
                    *(__half2*)(g_ohi + oidx) =
                        __floats2half2_rn(acc[nt][hf * 2], acc[nt][hf * 2 + 1]);
                }
            }
        }
    }
}

// ---------------------------------------------------------------------------
extern "C" void kernel_launch(void* const* d_in, const int* in_sizes, int n_in,
                              void* d_out, int out_size)
{
    const float* x           = (const float*)d_in[0];
    const float* mask        = (const float*)d_in[1];
    const float* w_qkv       = (const float*)d_in[2];
    const float* b_qkv       = (const float*)d_in[3];
    const float* w_proj      = (const float*)d_in[4];
    const float* b_proj      = (const float*)d_in[5];
    const float* bias_table  = (const float*)d_in[6];
    const int*   index_table = (const int*)d_in[7];
    float* out = (float*)d_out;

    static cudaStream_t sA = nullptr, sB = nullptr;
    static cudaEvent_t evF = nullptr, evA = nullptr, evB = nullptr;
    if (sA == nullptr) {
        int loPri, hiPri;  // loPri = least priority (numerically greatest)
        cudaDeviceGetStreamPriorityRange(&loPri, &hiPri);
        cudaStreamCreateWithPriority(&sA, cudaStreamNonBlocking, hiPri);
        cudaStreamCreateWithPriority(&sB, cudaStreamNonBlocking, loPri);
        cudaEventCreateWithFlags(&evF, cudaEventDisableTiming);
        cudaEventCreateWithFlags(&evA, cudaEventDisableTiming);
        cudaEventCreateWithFlags(&evB, cudaEventDisableTiming);
        cudaFuncSetAttribute(gemm_f16x3<1, 3>, cudaFuncAttributeMaxDynamicSharedMemorySize, DYN_SMEM);
        cudaFuncSetAttribute(gemm_f16x3<1, 1>, cudaFuncAttributeMaxDynamicSharedMemorySize, DYN_SMEM);
        cudaFuncSetAttribute(gemm_f16x3<2, 1>, cudaFuncAttributeMaxDynamicSharedMemorySize, DYN_SMEM);
    }

    // 0) preprocessing on the main (capture-origin) stream
    wtrans_kernel<1><<<dim3(NQKV / 32, KDIM / 32), dim3(32, 8)>>>(w_qkv, KDIM, NQKV);
    wtrans_kernel<2><<<dim3(CDIM / 32, KDIM / 32), dim3(32, 8)>>>(w_proj, KDIM, CDIM);
    split_x_kernel<<<((size_t)MROWS * CDIM) / 4 / 256, 256>>>(x);
    biasmask_kernel<<<64 * NHEAD, 256>>>(mask, bias_table, index_table);

    // fork both chains off the main stream
    cudaEventRecord(evF, 0);
    cudaStreamWaitEvent(sA, evF, 0);
    cudaStreamWaitEvent(sB, evF, 0);

    // Chain A (high priority): QK cols {0,1,4,5}, V cols {8,9},
    // windows 0..2047, out rows 0..100351
    gemm_f16x3<1, 3><<<dim3(4, MROWS / 128), 256, DYN_SMEM, sA>>>(b_qkv, nullptr, NQKV, 0, 0);
    gemm_f16x3<1, 1><<<dim3(2, MROWS / 128), 256, DYN_SMEM, sA>>>(b_qkv, nullptr, NQKV, 8, 0);
    attn_kernel<<<HALF_WIN * NHEAD, 256, 0, sA>>>(0);
    gemm_f16x3<2, 1><<<dim3(4, HALF_BM), 256, DYN_SMEM, sA>>>(b_proj, out, CDIM, 0, 0);
    cudaEventRecord(evA, sA);

    // Chain B (low priority): QK cols {2,3,6,7}, V cols {10,11},
    // windows 2048..4095, out rows 100352..200703
    gemm_f16x3<1, 3><<<dim3(4, MROWS / 128), 256, DYN_SMEM, sB>>>(b_qkv, nullptr, NQKV, 2, 0);
    gemm_f16x3<1, 1><<<dim3(2, MROWS / 128), 256, DYN_SMEM, sB>>>(b_qkv, nullptr, NQKV, 10, 0);
    attn_kernel<<<HALF_WIN * NHEAD, 256, 0, sB>>>(HALF_WIN);
    gemm_f16x3<2, 1><<<dim3(4, HALF_BM), 256, DYN_SMEM, sB>>>(b_proj, out, CDIM, 0, HALF_BM);
    cudaEventRecord(evB, sB);

    // join back to the main stream
    cudaStreamWaitEvent(0, evA, 0);
    cudaStreamWaitEvent(0, evB, 0);
}